// round 10
// baseline (speedup 1.0000x reference)
#include <cuda_runtime.h>
#include <cuda_bf16.h>
#include <cstdint>

#define LDF 68
#define LDA 72
#define XS_O 0u
#define QS_O 17408u
#define KS_O 34816u
#define VS_O 52224u
#define AH_O 69632u
#define AL_O 78848u
#define BH_O 88064u
#define BL_O 97280u
#define SMEMB 106496u
#define A2H_O 17408u
#define A2L_O 26624u

__device__ uint32_t g_wblob[48 * 4608];

__device__ __forceinline__ float fast_tanh(float x) { float r; asm("tanh.approx.f32 %0, %1;" : "=f"(r) : "f"(x)); return r; }
__device__ __forceinline__ float gelu_t(float x) {
    float t = fast_tanh(0.7978845608028654f * (x + 0.044715f * x * x * x));
    return 0.5f * x * (1.0f + t);
}
__device__ __forceinline__ uint32_t pack_hl(float v0, float v1, uint32_t& lo) {
    __nv_bfloat16 h0 = __float2bfloat16(v0), h1 = __float2bfloat16(v1);
    __nv_bfloat16 l0 = __float2bfloat16(v0 - __bfloat162float(h0));
    __nv_bfloat16 l1 = __float2bfloat16(v1 - __bfloat162float(h1));
    lo = (uint32_t)__bfloat16_as_ushort(l0) | ((uint32_t)__bfloat16_as_ushort(l1) << 16);
    return (uint32_t)__bfloat16_as_ushort(h0) | ((uint32_t)__bfloat16_as_ushort(h1) << 16);
}
__device__ __forceinline__ void ldmx4(uint32_t& r0, uint32_t& r1, uint32_t& r2, uint32_t& r3, uint32_t a) {
    asm volatile("ldmatrix.sync.aligned.m8n8.x4.shared.b16 {%0,%1,%2,%3}, [%4];"
        : "=r"(r0), "=r"(r1), "=r"(r2), "=r"(r3) : "r"(a));
}
__device__ __forceinline__ void ldmx4t(uint32_t& r0, uint32_t& r1, uint32_t& r2, uint32_t& r3, uint32_t a) {
    asm volatile("ldmatrix.sync.aligned.m8n8.x4.trans.shared.b16 {%0,%1,%2,%3}, [%4];"
        : "=r"(r0), "=r"(r1), "=r"(r2), "=r"(r3) : "r"(a));
}
__device__ __forceinline__ void mma16816(float (&c)[4], uint32_t a0, uint32_t a1, uint32_t a2, uint32_t a3,
                                         uint32_t b0, uint32_t b1) {
    asm volatile("mma.sync.aligned.m16n8k16.row.col.f32.bf16.bf16.f32 "
        "{%0,%1,%2,%3}, {%4,%5,%6,%7}, {%8,%9}, {%0,%1,%2,%3};"
        : "+f"(c[0]), "+f"(c[1]), "+f"(c[2]), "+f"(c[3])
        : "r"(a0), "r"(a1), "r"(a2), "r"(a3), "r"(b0), "r"(b1));
}

__global__ void prep_weights(const float* __restrict__ Wq, const float* __restrict__ Wk,
                             const float* __restrict__ Wv, const float* __restrict__ Wo,
                             const float* __restrict__ W1, const float* __restrict__ W2) {
    int s = blockIdx.x, l = s / 12, r = s % 12;
    for (int idx = threadIdx.x; idx < 2304; idx += blockDim.x) {
        int k = idx / 36, n2 = idx % 36;
        float vv[2];
        #pragma unroll
        for (int t = 0; t < 2; t++) {
            int c = 2 * n2 + t;
            float v = 0.f;
            if (r < 3) {
                const float* src = (r == 0 ? Wq : (r == 1 ? Wk : Wv)) + l * 3136;
                int hd = c >> 3, di = c & 7;
                if (k < 56 && c < 64 && di < 7) v = src[k * 56 + hd * 7 + di];
            } else if (r == 3) {
                const float* src = Wo + l * 3136;
                int hk = k >> 3, ki = k & 7;
                if (c < 56 && k < 64 && ki < 7) v = src[(hk * 7 + ki) * 56 + c];
            } else if (r < 8) {
                const float* src = W1 + l * 12544;
                if (k < 56 && c < 56) v = src[k * 224 + (r - 4) * 56 + c];
            } else {
                const float* src = W2 + l * 12544;
                if (k < 56 && c < 56) v = src[((r - 8) * 56 + k) * 56 + c];
            }
            vv[t] = v;
        }
        uint32_t lo, hi = pack_hl(vv[0], vv[1], lo);
        g_wblob[s * 4608 + idx] = hi;
        g_wblob[s * 4608 + 2304 + idx] = lo;
    }
}

struct BR { uint4 a, b, c, d, e; };
__device__ __forceinline__ void ldb(BR& br, int s, int tid) {
    const uint4* p = (const uint4*)(g_wblob + s * 4608);
    br.a = __ldg(p + tid);       br.b = __ldg(p + tid + 256);
    br.c = __ldg(p + tid + 512); br.d = __ldg(p + tid + 768);
    if (tid < 128) br.e = __ldg(p + tid + 1024);
}
__device__ __forceinline__ void stb(char* sm, const BR& br, int tid) {
    uint4* d = (uint4*)(sm + BH_O);
    d[tid] = br.a; d[tid + 256] = br.b; d[tid + 512] = br.c; d[tid + 768] = br.d;
    if (tid < 128) d[tid + 1024] = br.e;
}

// load A fragments (hi+lo, 4 k-steps) for this warp's 16-row strip
__device__ __forceinline__ void loadA(uint32_t smb, uint32_t ahO, uint32_t alO, int tid, uint32_t* A) {
    int lane = tid & 31, mt = (tid >> 5) >> 1;
    uint32_t aoff = ((uint32_t)(mt * 16 + (lane & 15)) * LDA + 8 * (lane >> 4)) * 2;
    uint32_t ahA = smb + ahO + aoff, alA = smb + alO + aoff;
    #pragma unroll
    for (int ks = 0; ks < 4; ks++) {
        ldmx4(A[ks * 8], A[ks * 8 + 1], A[ks * 8 + 2], A[ks * 8 + 3], ahA + ks * 32);
        ldmx4(A[ks * 8 + 4], A[ks * 8 + 5], A[ks * 8 + 6], A[ks * 8 + 7], alA + ks * 32);
    }
}

// GEMM body with preloaded A fragments
template <int MODE>
__device__ __forceinline__ void gemm_core(char* sm, uint32_t smb, const uint32_t* A,
                                          float* __restrict__ Dbuf, const float* __restrict__ bias, int tid) {
    const int lane = tid & 31, warp = tid >> 5;
    const int mt = warp >> 1, nh = warp & 1;
    float c[4][4];
    #pragma unroll
    for (int j = 0; j < 4; j++) c[j][0] = c[j][1] = c[j][2] = c[j][3] = 0.f;
    int bg = lane >> 3, bi = lane & 7;
    uint32_t boff0 = ((uint32_t)((bg & 1) * 8 + bi) * LDA + nh * 32 + (bg >> 1) * 8) * 2;
    uint32_t bhA = smb + BH_O + boff0, blA = smb + BL_O + boff0;
    #pragma unroll
    for (int ks = 0; ks < 4; ks++) {
        uint32_t kr = ks * (16 * LDA * 2);
        uint32_t bh[8], bl[8];
        ldmx4t(bh[0], bh[1], bh[2], bh[3], bhA + kr);
        ldmx4t(bh[4], bh[5], bh[6], bh[7], bhA + kr + 32);
        ldmx4t(bl[0], bl[1], bl[2], bl[3], blA + kr);
        ldmx4t(bl[4], bl[5], bl[6], bl[7], blA + kr + 32);
        const uint32_t* a = A + ks * 8;
        #pragma unroll
        for (int j = 0; j < 4; j++) {
            mma16816(c[j], a[0], a[1], a[2], a[3], bh[2 * j], bh[2 * j + 1]);
            mma16816(c[j], a[0], a[1], a[2], a[3], bl[2 * j], bl[2 * j + 1]);
            mma16816(c[j], a[4], a[5], a[6], a[7], bh[2 * j], bh[2 * j + 1]);
        }
    }
    const int r0 = mt * 16 + (lane >> 2);
    const int cq = (lane & 3) * 2;
    #pragma unroll
    for (int j = 0; j < 4; j++) {
        int col = nh * 32 + j * 8 + cq;
        if (MODE == 0) {
            *(float2*)(Dbuf + r0 * LDF + col)       = make_float2(c[j][0], c[j][1]);
            *(float2*)(Dbuf + (r0 + 8) * LDF + col) = make_float2(c[j][2], c[j][3]);
        } else if (MODE == 1) {
            float2 p0 = *(float2*)(Dbuf + r0 * LDF + col);
            float2 p1 = *(float2*)(Dbuf + (r0 + 8) * LDF + col);
            p0.x += c[j][0]; p0.y += c[j][1]; p1.x += c[j][2]; p1.y += c[j][3];
            *(float2*)(Dbuf + r0 * LDF + col)       = p0;
            *(float2*)(Dbuf + (r0 + 8) * LDF + col) = p1;
        } else {
            uint32_t h0 = 0, lo0 = 0, h1 = 0, lo1 = 0;
            if (!(nh == 1 && j == 3)) {
                float b0 = __ldg(bias + col), b1 = __ldg(bias + col + 1);
                h0 = pack_hl(gelu_t(c[j][0] + b0), gelu_t(c[j][1] + b1), lo0);
                h1 = pack_hl(gelu_t(c[j][2] + b0), gelu_t(c[j][3] + b1), lo1);
            }
            uint32_t o0 = ((uint32_t)(r0 * LDA + col)) * 2, o1 = ((uint32_t)((r0 + 8) * LDA + col)) * 2;
            *(uint32_t*)(sm + A2H_O + o0) = h0;  *(uint32_t*)(sm + A2L_O + o0) = lo0;
            *(uint32_t*)(sm + A2H_O + o1) = h1;  *(uint32_t*)(sm + A2L_O + o1) = lo1;
        }
    }
}

// self-loading variant (no persistent A regs)
template <int MODE>
__device__ __forceinline__ void gemm_m(char* sm, uint32_t smb, uint32_t ahO, uint32_t alO,
                                       float* __restrict__ Dbuf, const float* __restrict__ bias, int tid) {
    uint32_t A[32];
    loadA(smb, ahO, alO, tid, A);
    gemm_core<MODE>(sm, smb, A, Dbuf, bias, tid);
}

template <bool ADDB>
__device__ __forceinline__ void row_cvt_ln(float* __restrict__ xs, const float* __restrict__ g,
                                           const float* __restrict__ b, const float* __restrict__ b2,
                                           char* sm, int tid) {
    int r = tid >> 2, part = tid & 3;
    float* xr = xs + r * LDF + part * 14;
    float v[14];
    #pragma unroll
    for (int j = 0; j < 7; j++) *(float2*)(v + 2 * j) = *(const float2*)(xr + 2 * j);
    float s = 0.f, ss = 0.f;
    #pragma unroll
    for (int j = 0; j < 14; j++) { s += v[j]; ss += v[j] * v[j]; }
    s  += __shfl_xor_sync(0xffffffffu, s, 1);
    ss += __shfl_xor_sync(0xffffffffu, ss, 1);
    s  += __shfl_xor_sync(0xffffffffu, s, 2);
    ss += __shfl_xor_sync(0xffffffffu, ss, 2);
    if (ADDB) {
        #pragma unroll
        for (int j = 0; j < 14; j++) xr[j] = v[j] + __ldg(b2 + part * 14 + j);
    }
    float m = s * (1.f / 56.f), rs = rsqrtf(ss * (1.f / 56.f) - m * m + 1e-5f);
    uint32_t* ah = (uint32_t*)(sm + AH_O + ((uint32_t)(r * LDA + part * 14)) * 2);
    uint32_t* al = (uint32_t*)(sm + AL_O + ((uint32_t)(r * LDA + part * 14)) * 2);
    #pragma unroll
    for (int t = 0; t < 7; t++) {
        int cl = part * 14 + 2 * t;
        float v0 = (v[2 * t]     - m) * rs * __ldg(g + cl)     + __ldg(b + cl);
        float v1 = (v[2 * t + 1] - m) * rs * __ldg(g + cl + 1) + __ldg(b + cl + 1);
        uint32_t lo, hi = pack_hl(v0, v1, lo);
        ah[t] = hi; al[t] = lo;
    }
}

__global__ void __launch_bounds__(256, 2)
nbody_tc(const float* __restrict__ nodes, const float* __restrict__ edges,
         const float* __restrict__ mask,
         const float* __restrict__ W_in, const float* __restrict__ b_in,
         const float* __restrict__ W_gp, const float* __restrict__ b_gp,
         const float* __restrict__ ln1g, const float* __restrict__ ln1b,
         const float* __restrict__ ln2g, const float* __restrict__ ln2b,
         const float* __restrict__ b1, const float* __restrict__ b2,
         float* __restrict__ out, int Btot) {
    extern __shared__ char sm[];
    const int tid = threadIdx.x, bx = blockIdx.x;
    const uint32_t smb = (uint32_t)__cvta_generic_to_shared(sm);
    float* xs = (float*)(sm + XS_O);
    float* qs = (float*)(sm + QS_O);
    float* ks = (float*)(sm + KS_O);
    float* vs = (float*)(sm + VS_O);
    BR br;
    ldb(br, 0, tid);

    #pragma unroll 1
    for (int i = tid; i < 64 * LDF / 4; i += 256) ((float4*)xs)[i] = make_float4(0.f, 0.f, 0.f, 0.f);
    if (tid < 128) {
        int buf = tid >> 6, r = tid & 63;
        *(uint4*)(sm + AH_O + (uint32_t)buf * (AL_O - AH_O) + ((uint32_t)(r * LDA + 56)) * 2) = make_uint4(0u, 0u, 0u, 0u);
    }

    if (tid < 50) {
        int g = tid / 25, s = tid % 25;
        long Bi = (long)bx * 2 + g;
        if (Bi < Btot) {
            const float* sp = (s < 5) ? nodes + (Bi * 5 + s) * 24 : edges + (Bi * 20 + (s - 5)) * 24;
            float xin[24];
            #pragma unroll
            for (int i = 0; i < 24; i++) xin[i] = __ldg(sp + i);
            const int GR[8] = {0, 1, 1, 1, 2, 2, 2, 3};
            const int POS[8] = {0, 1, 2, 4, 3, 5, 6, 7};
            float* xrow = xs + (g * 32 + s) * LDF;
            #pragma unroll 1
            for (int n = 0; n < 7; n++) {
                float acc[8];
                #pragma unroll
                for (int i = 0; i < 8; i++) acc[i] = (i == 0) ? __ldg(b_gp + n) : 0.f;
                #pragma unroll 1
                for (int m = 0; m < 7; m++) {
                    float mv[8];
                    #pragma unroll
                    for (int i = 0; i < 8; i++) {
                        int gr = GR[i];
                        mv[i] = xin[i] * __ldg(W_in + m * 12 + gr) + xin[8 + i] * __ldg(W_in + m * 12 + 4 + gr)
                              + xin[16 + i] * __ldg(W_in + m * 12 + 8 + gr);
                    }
                    mv[0] += __ldg(b_in + m);
                    float gp[8];
                    #pragma unroll
                    for (int j = 0; j < 8; j++) gp[j] = 0.f;
                    #pragma unroll
                    for (int a = 0; a < 8; a++)
                        #pragma unroll
                        for (int bb = 0; bb < 8; bb++) {
                            int sc = 0;
                            #pragma unroll
                            for (int t = a >> 1; t; t >>= 1) sc += __popc(t & bb);
                            gp[POS[a ^ bb]] += ((sc & 1) ? -1.f : 1.f) * mv[POS[a]] * mv[POS[bb]];
                        }
                    #pragma unroll
                    for (int i = 0; i < 8; i++) {
                        int gr = GR[i];
                        acc[i] += mv[i] * __ldg(W_gp + n * 56 + m * 4 + gr)
                                + gp[i] * __ldg(W_gp + n * 56 + (m + 7) * 4 + gr);
                    }
                }
                #pragma unroll
                for (int i = 0; i < 8; i++) xrow[n * 8 + i] = acc[i];
            }
        }
    }
    __syncthreads();
    stb(sm, br, tid);
    __syncthreads();

    #pragma unroll 1
    for (int l = 0; l < 4; l++) {
        const int sbase = l * 12;
        row_cvt_ln<false>(xs, ln1g + l * 56, ln1b + l * 56, nullptr, sm, tid);
        __syncthreads();

        {   // QKV: A frags loaded once, reused 3x
            uint32_t Af[32];
            loadA(smb, AH_O, AL_O, tid, Af);
            ldb(br, sbase + 1, tid);
            gemm_core<0>(sm, smb, Af, qs, nullptr, tid);
            __syncthreads(); stb(sm, br, tid); __syncthreads();
            ldb(br, sbase + 2, tid);
            gemm_core<0>(sm, smb, Af, ks, nullptr, tid);
            __syncthreads(); stb(sm, br, tid); __syncthreads();
            ldb(br, sbase + 3, tid);
            gemm_core<0>(sm, smb, Af, vs, nullptr, tid);
            __syncthreads(); stb(sm, br, tid); __syncthreads();
        }

        // broadcast attention: warp = (g, head), lane = query s; fully unrolled
        {
            int lane = tid & 31, w = tid >> 5;
            #pragma unroll
            for (int rep = 0; rep < 2; rep++) {
                int pair = w + rep * 8;
                int g = pair >> 3, hh = pair & 7;
                long Bi = (long)bx * 2 + g;
                long Bic = (Bi < Btot) ? Bi : (long)(Btot - 1);
                int s = (lane < 25) ? lane : 24;
                int rq = (g * 32 + s) * LDF + hh * 8;
                float4 q0 = *(const float4*)(qs + rq), q1 = *(const float4*)(qs + rq + 4);
                const float* mrow = mask + (Bic * 25 + s) * 25;
                float sc[25]; float mx = -1e30f;
                #pragma unroll
                for (int ki = 0; ki < 25; ki++) {
                    const float* kp = ks + (g * 32 + ki) * LDF + hh * 8;
                    float4 k0 = *(const float4*)(kp), k1 = *(const float4*)(kp + 4);
                    float dot = q0.x * k0.x + q0.y * k0.y + q0.z * k0.z + q0.w * k0.w
                              + q1.x * k1.x + q1.y * k1.y + q1.z * k1.z + q1.w * k1.w;
                    sc[ki] = dot * 0.3779644730092272f + __ldg(mrow + ki);
                    mx = fmaxf(mx, sc[ki]);
                }
                float sum = 0.f;
                #pragma unroll
                for (int ki = 0; ki < 25; ki++) { float e = __expf(sc[ki] - mx); sc[ki] = e; sum += e; }
                float inv = 1.f / sum;
                float4 o0 = make_float4(0.f, 0.f, 0.f, 0.f), o1 = o0;
                #pragma unroll
                for (int ki = 0; ki < 25; ki++) {
                    const float* vp = vs + (g * 32 + ki) * LDF + hh * 8;
                    float4 v0 = *(const float4*)(vp), v1 = *(const float4*)(vp + 4);
                    float p = sc[ki];
                    o0.x += p * v0.x; o0.y += p * v0.y; o0.z += p * v0.z; o0.w += p * v0.w;
                    o1.x += p * v1.x; o1.y += p * v1.y; o1.z += p * v1.z; o1.w += p * v1.w;
                }
                if (lane < 25) {
                    uint32_t ob = ((uint32_t)((g * 32 + lane) * LDA + hh * 8)) * 2;
                    uint4 H, L;
                    H.x = pack_hl(o0.x * inv, o0.y * inv, L.x);
                    H.y = pack_hl(o0.z * inv, o0.w * inv, L.y);
                    H.z = pack_hl(o1.x * inv, o1.y * inv, L.z);
                    H.w = pack_hl(o1.z * inv, o1.w * inv, L.w);
                    *(uint4*)(sm + AH_O + ob) = H;
                    *(uint4*)(sm + AL_O + ob) = L;
                }
            }
        }
        __syncthreads();

        ldb(br, sbase + 4, tid);
        gemm_m<1>(sm, smb, AH_O, AL_O, xs, nullptr, tid);   // x += o @ Wo
        __syncthreads(); stb(sm, br, tid); __syncthreads();

        row_cvt_ln<true>(xs, ln2g + l * 56, ln2b + l * 56, b2 + l * 56, sm, tid);
        __syncthreads();

        #pragma unroll 1
        for (int c = 0; c < 4; c++) {
            ldb(br, sbase + 8 + c, tid);
            gemm_m<2>(sm, smb, AH_O, AL_O, nullptr, b1 + l * 224 + c * 56, tid);
            __syncthreads(); stb(sm, br, tid); __syncthreads();
            int nxt = (c < 3) ? (sbase + 5 + c) : ((l < 3) ? (sbase + 12) : 0);
            ldb(br, nxt, tid);
            gemm_m<1>(sm, smb, A2H_O, A2L_O, xs, nullptr, tid);
            __syncthreads(); stb(sm, br, tid); __syncthreads();
        }
    }

    if (tid < 80) {
        int g = tid / 40, r = tid % 40, s = r / 8, i = r % 8;
        long Bi = (long)bx * 2 + g;
        if (Bi < Btot) out[(Bi * 5 + s) * 8 + i] = xs[(g * 32 + s) * LDF + 8 + i];
    }
}

extern "C" void kernel_launch(void* const* d_in, const int* in_sizes, int n_in,
                              void* d_out, int out_size) {
    int o = (n_in >= 20) ? 4 : 3;
    const float* nodes = (const float*)d_in[0];
    const float* edges = (const float*)d_in[1];
    const float* mask  = (const float*)d_in[2];
    const float* W_in  = (const float*)d_in[o + 0];
    const float* b_in  = (const float*)d_in[o + 1];
    const float* W_gp  = (const float*)d_in[o + 2];
    const float* b_gp  = (const float*)d_in[o + 3];
    const float* Wq    = (const float*)d_in[o + 4];
    const float* Wk    = (const float*)d_in[o + 5];
    const float* Wv    = (const float*)d_in[o + 6];
    const float* Wo    = (const float*)d_in[o + 7];
    const float* ln1g  = (const float*)d_in[o + 8];
    const float* ln1b  = (const float*)d_in[o + 9];
    const float* ln2g  = (const float*)d_in[o + 10];
    const float* ln2b  = (const float*)d_in[o + 11];
    const float* W1    = (const float*)d_in[o + 12];
    const float* b1    = (const float*)d_in[o + 13];
    const float* W2    = (const float*)d_in[o + 14];
    const float* b2    = (const float*)d_in[o + 15];

    int B = in_sizes[0] / 120;
    prep_weights<<<48, 256>>>(Wq, Wk, Wv, Wo, W1, W2);
    cudaFuncSetAttribute(nbody_tc, cudaFuncAttributeMaxDynamicSharedMemorySize, SMEMB);
    nbody_tc<<<(B + 1) / 2, 256, SMEMB>>>(nodes, edges, mask, W_in, b_in, W_gp, b_gp,
                                          ln1g, ln1b, ln2g, ln2b, b1, b2, (float*)d_out, B);
}

// round 11
// speedup vs baseline: 1.5295x; 1.5295x over previous
#include <cuda_runtime.h>
#include <cuda_bf16.h>
#include <cstdint>

#define LDF 68
#define LDA 72
#define XS_O 0u
#define QS_O 17408u
#define KS_O 34816u
#define VS_O 52224u
#define AH_O 69632u
#define AL_O 78848u
#define BH_O 88064u
#define BL_O 97280u
#define SMEMB 106496u
#define A2H_O 17408u
#define A2L_O 26624u

__device__ uint32_t g_wblob[48 * 4608];

__device__ __forceinline__ float fast_tanh(float x) { float r; asm("tanh.approx.f32 %0, %1;" : "=f"(r) : "f"(x)); return r; }
__device__ __forceinline__ float gelu_t(float x) {
    float t = fast_tanh(0.7978845608028654f * (x + 0.044715f * x * x * x));
    return 0.5f * x * (1.0f + t);
}
__device__ __forceinline__ uint32_t pack_hl(float v0, float v1, uint32_t& lo) {
    __nv_bfloat16 h0 = __float2bfloat16(v0), h1 = __float2bfloat16(v1);
    __nv_bfloat16 l0 = __float2bfloat16(v0 - __bfloat162float(h0));
    __nv_bfloat16 l1 = __float2bfloat16(v1 - __bfloat162float(h1));
    lo = (uint32_t)__bfloat16_as_ushort(l0) | ((uint32_t)__bfloat16_as_ushort(l1) << 16);
    return (uint32_t)__bfloat16_as_ushort(h0) | ((uint32_t)__bfloat16_as_ushort(h1) << 16);
}
__device__ __forceinline__ void ldmx4(uint32_t& r0, uint32_t& r1, uint32_t& r2, uint32_t& r3, uint32_t a) {
    asm volatile("ldmatrix.sync.aligned.m8n8.x4.shared.b16 {%0,%1,%2,%3}, [%4];"
        : "=r"(r0), "=r"(r1), "=r"(r2), "=r"(r3) : "r"(a));
}
__device__ __forceinline__ void ldmx4t(uint32_t& r0, uint32_t& r1, uint32_t& r2, uint32_t& r3, uint32_t a) {
    asm volatile("ldmatrix.sync.aligned.m8n8.x4.trans.shared.b16 {%0,%1,%2,%3}, [%4];"
        : "=r"(r0), "=r"(r1), "=r"(r2), "=r"(r3) : "r"(a));
}
__device__ __forceinline__ void mma16816(float (&c)[4], uint32_t a0, uint32_t a1, uint32_t a2, uint32_t a3,
                                         uint32_t b0, uint32_t b1) {
    asm volatile("mma.sync.aligned.m16n8k16.row.col.f32.bf16.bf16.f32 "
        "{%0,%1,%2,%3}, {%4,%5,%6,%7}, {%8,%9}, {%0,%1,%2,%3};"
        : "+f"(c[0]), "+f"(c[1]), "+f"(c[2]), "+f"(c[3])
        : "r"(a0), "r"(a1), "r"(a2), "r"(a3), "r"(b0), "r"(b1));
}

__global__ void prep_weights(const float* __restrict__ Wq, const float* __restrict__ Wk,
                             const float* __restrict__ Wv, const float* __restrict__ Wo,
                             const float* __restrict__ W1, const float* __restrict__ W2) {
    int s = blockIdx.x, l = s / 12, r = s % 12;
    for (int idx = threadIdx.x; idx < 2304; idx += blockDim.x) {
        int k = idx / 36, n2 = idx % 36;
        float vv[2];
        #pragma unroll
        for (int t = 0; t < 2; t++) {
            int c = 2 * n2 + t;
            float v = 0.f;
            if (r < 3) {
                const float* src = (r == 0 ? Wq : (r == 1 ? Wk : Wv)) + l * 3136;
                int hd = c >> 3, di = c & 7;
                if (k < 56 && c < 64 && di < 7) v = src[k * 56 + hd * 7 + di];
            } else if (r == 3) {
                const float* src = Wo + l * 3136;
                int hk = k >> 3, ki = k & 7;
                if (c < 56 && k < 64 && ki < 7) v = src[(hk * 7 + ki) * 56 + c];
            } else if (r < 8) {
                const float* src = W1 + l * 12544;
                if (k < 56 && c < 56) v = src[k * 224 + (r - 4) * 56 + c];
            } else {
                const float* src = W2 + l * 12544;
                if (k < 56 && c < 56) v = src[((r - 8) * 56 + k) * 56 + c];
            }
            vv[t] = v;
        }
        uint32_t lo, hi = pack_hl(vv[0], vv[1], lo);
        g_wblob[s * 4608 + idx] = hi;
        g_wblob[s * 4608 + 2304 + idx] = lo;
    }
}

struct BR { uint4 a, b, c, d, e; };
__device__ __forceinline__ void ldb(BR& br, int s, int tid) {
    const uint4* p = (const uint4*)(g_wblob + s * 4608);
    br.a = __ldg(p + tid);       br.b = __ldg(p + tid + 256);
    br.c = __ldg(p + tid + 512); br.d = __ldg(p + tid + 768);
    if (tid < 128) br.e = __ldg(p + tid + 1024);
}
__device__ __forceinline__ void stb(char* sm, const BR& br, int tid) {
    uint4* d = (uint4*)(sm + BH_O);
    d[tid] = br.a; d[tid + 256] = br.b; d[tid + 512] = br.c; d[tid + 768] = br.d;
    if (tid < 128) d[tid + 1024] = br.e;
}

// ---- GEMM: inline A loads (short live ranges, no spills). MODE: 0 store, 1 +=, 2 gelu->A2 ----
template <int MODE>
__device__ __forceinline__ void gemm_m(char* sm, uint32_t smb, uint32_t ahO, uint32_t alO,
                                       float* __restrict__ Dbuf, const float* __restrict__ bias, int tid) {
    const int lane = tid & 31, warp = tid >> 5;
    const int mt = warp >> 1, nh = warp & 1;
    float c[4][4];
    #pragma unroll
    for (int j = 0; j < 4; j++) { c[j][0] = c[j][1] = c[j][2] = c[j][3] = 0.f; }

    uint32_t aoff = ((uint32_t)(mt * 16 + (lane & 15)) * LDA + 8 * (lane >> 4)) * 2;
    uint32_t ahA = smb + ahO + aoff, alA = smb + alO + aoff;
    int bg = lane >> 3, bi = lane & 7;
    uint32_t boff0 = ((uint32_t)((bg & 1) * 8 + bi) * LDA + nh * 32 + (bg >> 1) * 8) * 2;
    uint32_t bhA = smb + BH_O + boff0, blA = smb + BL_O + boff0;

    #pragma unroll
    for (int ks = 0; ks < 4; ks++) {
        uint32_t kb = ks * 32;
        uint32_t kr = ks * (16 * LDA * 2);
        uint32_t a0, a1, a2, a3, l0, l1, l2, l3;
        ldmx4 (a0, a1, a2, a3, ahA + kb);
        ldmx4 (l0, l1, l2, l3, alA + kb);
        uint32_t bh[8], bl[8];
        ldmx4t(bh[0], bh[1], bh[2], bh[3], bhA + kr);
        ldmx4t(bh[4], bh[5], bh[6], bh[7], bhA + kr + 32);
        ldmx4t(bl[0], bl[1], bl[2], bl[3], blA + kr);
        ldmx4t(bl[4], bl[5], bl[6], bl[7], blA + kr + 32);
        #pragma unroll
        for (int j = 0; j < 4; j++) {
            mma16816(c[j], a0, a1, a2, a3, bh[2 * j], bh[2 * j + 1]);
            mma16816(c[j], a0, a1, a2, a3, bl[2 * j], bl[2 * j + 1]);
            mma16816(c[j], l0, l1, l2, l3, bh[2 * j], bh[2 * j + 1]);
        }
    }

    const int r0 = mt * 16 + (lane >> 2);
    const int cq = (lane & 3) * 2;
    #pragma unroll
    for (int j = 0; j < 4; j++) {
        int col = nh * 32 + j * 8 + cq;
        if (MODE == 0) {
            *(float2*)(Dbuf + r0 * LDF + col)       = make_float2(c[j][0], c[j][1]);
            *(float2*)(Dbuf + (r0 + 8) * LDF + col) = make_float2(c[j][2], c[j][3]);
        } else if (MODE == 1) {
            float2 p0 = *(float2*)(Dbuf + r0 * LDF + col);
            float2 p1 = *(float2*)(Dbuf + (r0 + 8) * LDF + col);
            p0.x += c[j][0]; p0.y += c[j][1]; p1.x += c[j][2]; p1.y += c[j][3];
            *(float2*)(Dbuf + r0 * LDF + col)       = p0;
            *(float2*)(Dbuf + (r0 + 8) * LDF + col) = p1;
        } else {
            uint32_t h0 = 0, lo0 = 0, h1 = 0, lo1 = 0;
            if (!(nh == 1 && j == 3)) {
                float b0 = __ldg(bias + col), b1 = __ldg(bias + col + 1);
                h0 = pack_hl(gelu_t(c[j][0] + b0), gelu_t(c[j][1] + b1), lo0);
                h1 = pack_hl(gelu_t(c[j][2] + b0), gelu_t(c[j][3] + b1), lo1);
            }
            uint32_t o0 = ((uint32_t)(r0 * LDA + col)) * 2, o1 = ((uint32_t)((r0 + 8) * LDA + col)) * 2;
            *(uint32_t*)(sm + A2H_O + o0) = h0;  *(uint32_t*)(sm + A2L_O + o0) = lo0;
            *(uint32_t*)(sm + A2H_O + o1) = h1;  *(uint32_t*)(sm + A2L_O + o1) = lo1;
        }
    }
}

template <bool ADDB>
__device__ __forceinline__ void row_cvt_ln(float* __restrict__ xs, const float* __restrict__ g,
                                           const float* __restrict__ b, const float* __restrict__ b2,
                                           char* sm, int tid) {
    int r = tid >> 2, part = tid & 3;
    float* xr = xs + r * LDF + part * 14;
    float v[14];
    #pragma unroll
    for (int j = 0; j < 7; j++) *(float2*)(v + 2 * j) = *(const float2*)(xr + 2 * j);
    float s = 0.f, ss = 0.f;
    #pragma unroll
    for (int j = 0; j < 14; j++) { s += v[j]; ss += v[j] * v[j]; }
    s  += __shfl_xor_sync(0xffffffffu, s, 1);
    ss += __shfl_xor_sync(0xffffffffu, ss, 1);
    s  += __shfl_xor_sync(0xffffffffu, s, 2);
    ss += __shfl_xor_sync(0xffffffffu, ss, 2);
    if (ADDB) {
        #pragma unroll
        for (int j = 0; j < 14; j++) xr[j] = v[j] + __ldg(b2 + part * 14 + j);
    }
    float m = s * (1.f / 56.f), rs = rsqrtf(ss * (1.f / 56.f) - m * m + 1e-5f);
    uint32_t* ah = (uint32_t*)(sm + AH_O + ((uint32_t)(r * LDA + part * 14)) * 2);
    uint32_t* al = (uint32_t*)(sm + AL_O + ((uint32_t)(r * LDA + part * 14)) * 2);
    #pragma unroll
    for (int t = 0; t < 7; t++) {
        int cl = part * 14 + 2 * t;
        float v0 = (v[2 * t]     - m) * rs * __ldg(g + cl)     + __ldg(b + cl);
        float v1 = (v[2 * t + 1] - m) * rs * __ldg(g + cl + 1) + __ldg(b + cl + 1);
        uint32_t lo, hi = pack_hl(v0, v1, lo);
        ah[t] = hi; al[t] = lo;
    }
}

__global__ void __launch_bounds__(256, 2)
nbody_tc(const float* __restrict__ nodes, const float* __restrict__ edges,
         const float* __restrict__ mask,
         const float* __restrict__ W_in, const float* __restrict__ b_in,
         const float* __restrict__ W_gp, const float* __restrict__ b_gp,
         const float* __restrict__ ln1g, const float* __restrict__ ln1b,
         const float* __restrict__ ln2g, const float* __restrict__ ln2b,
         const float* __restrict__ b1, const float* __restrict__ b2,
         float* __restrict__ out, int Btot) {
    extern __shared__ char sm[];
    const int tid = threadIdx.x, bx = blockIdx.x;
    const uint32_t smb = (uint32_t)__cvta_generic_to_shared(sm);
    float* xs = (float*)(sm + XS_O);
    float* qs = (float*)(sm + QS_O);
    float* ks = (float*)(sm + KS_O);
    float* vs = (float*)(sm + VS_O);
    BR br;
    ldb(br, 0, tid);

    #pragma unroll 1
    for (int i = tid; i < 64 * LDF / 4; i += 256) ((float4*)xs)[i] = make_float4(0.f, 0.f, 0.f, 0.f);
    if (tid < 128) {
        int buf = tid >> 6, r = tid & 63;
        *(uint4*)(sm + AH_O + (uint32_t)buf * (AL_O - AH_O) + ((uint32_t)(r * LDA + 56)) * 2) = make_uint4(0u, 0u, 0u, 0u);
    }

    if (tid < 50) {
        int g = tid / 25, s = tid % 25;
        long Bi = (long)bx * 2 + g;
        if (Bi < Btot) {
            const float* sp = (s < 5) ? nodes + (Bi * 5 + s) * 24 : edges + (Bi * 20 + (s - 5)) * 24;
            float xin[24];
            #pragma unroll
            for (int i = 0; i < 24; i++) xin[i] = __ldg(sp + i);
            const int GR[8] = {0, 1, 1, 1, 2, 2, 2, 3};
            const int POS[8] = {0, 1, 2, 4, 3, 5, 6, 7};
            float* xrow = xs + (g * 32 + s) * LDF;
            #pragma unroll 1
            for (int n = 0; n < 7; n++) {
                float acc[8];
                #pragma unroll
                for (int i = 0; i < 8; i++) acc[i] = (i == 0) ? __ldg(b_gp + n) : 0.f;
                #pragma unroll 1
                for (int m = 0; m < 7; m++) {
                    float mv[8];
                    #pragma unroll
                    for (int i = 0; i < 8; i++) {
                        int gr = GR[i];
                        mv[i] = xin[i] * __ldg(W_in + m * 12 + gr) + xin[8 + i] * __ldg(W_in + m * 12 + 4 + gr)
                              + xin[16 + i] * __ldg(W_in + m * 12 + 8 + gr);
                    }
                    mv[0] += __ldg(b_in + m);
                    float gp[8];
                    #pragma unroll
                    for (int j = 0; j < 8; j++) gp[j] = 0.f;
                    #pragma unroll
                    for (int a = 0; a < 8; a++)
                        #pragma unroll
                        for (int bb = 0; bb < 8; bb++) {
                            int sc = 0;
                            #pragma unroll
                            for (int t = a >> 1; t; t >>= 1) sc += __popc(t & bb);
                            gp[POS[a ^ bb]] += ((sc & 1) ? -1.f : 1.f) * mv[POS[a]] * mv[POS[bb]];
                        }
                    #pragma unroll
                    for (int i = 0; i < 8; i++) {
                        int gr = GR[i];
                        acc[i] += mv[i] * __ldg(W_gp + n * 56 + m * 4 + gr)
                                + gp[i] * __ldg(W_gp + n * 56 + (m + 7) * 4 + gr);
                    }
                }
                #pragma unroll
                for (int i = 0; i < 8; i++) xrow[n * 8 + i] = acc[i];
            }
        }
    }
    __syncthreads();
    stb(sm, br, tid);
    __syncthreads();

    #pragma unroll 1
    for (int l = 0; l < 4; l++) {
        const int sbase = l * 12;
        row_cvt_ln<false>(xs, ln1g + l * 56, ln1b + l * 56, nullptr, sm, tid);
        __syncthreads();

        ldb(br, sbase + 1, tid);
        gemm_m<0>(sm, smb, AH_O, AL_O, qs, nullptr, tid);
        __syncthreads(); stb(sm, br, tid); __syncthreads();
        ldb(br, sbase + 2, tid);
        gemm_m<0>(sm, smb, AH_O, AL_O, ks, nullptr, tid);
        __syncthreads(); stb(sm, br, tid); __syncthreads();
        ldb(br, sbase + 3, tid);
        gemm_m<0>(sm, smb, AH_O, AL_O, vs, nullptr, tid);
        __syncthreads(); stb(sm, br, tid); __syncthreads();

        // broadcast attention: warp = (g, head), lane = query s; K/V rows uniform across warp
        {
            int lane = tid & 31, w = tid >> 5;
            #pragma unroll
            for (int rep = 0; rep < 2; rep++) {
                int pair = w + rep * 8;
                int g = pair >> 3, hh = pair & 7;
                long Bi = (long)bx * 2 + g;
                long Bic = (Bi < Btot) ? Bi : (long)(Btot - 1);
                int s = (lane < 25) ? lane : 24;
                int rq = (g * 32 + s) * LDF + hh * 8;
                float4 q0 = *(const float4*)(qs + rq), q1 = *(const float4*)(qs + rq + 4);
                const float* mrow = mask + (Bic * 25 + s) * 25;
                float sc[25]; float mx = -1e30f;
                #pragma unroll
                for (int ki = 0; ki < 25; ki++) {
                    const float* kp = ks + (g * 32 + ki) * LDF + hh * 8;
                    float4 k0 = *(const float4*)(kp), k1 = *(const float4*)(kp + 4);
                    float dot = q0.x * k0.x + q0.y * k0.y + q0.z * k0.z + q0.w * k0.w
                              + q1.x * k1.x + q1.y * k1.y + q1.z * k1.z + q1.w * k1.w;
                    sc[ki] = dot * 0.3779644730092272f + __ldg(mrow + ki);
                    mx = fmaxf(mx, sc[ki]);
                }
                float sum = 0.f;
                #pragma unroll
                for (int ki = 0; ki < 25; ki++) { float e = __expf(sc[ki] - mx); sc[ki] = e; sum += e; }
                float inv = 1.f / sum;
                float4 o0 = make_float4(0.f, 0.f, 0.f, 0.f), o1 = o0;
                #pragma unroll
                for (int ki = 0; ki < 25; ki++) {
                    const float* vp = vs + (g * 32 + ki) * LDF + hh * 8;
                    float4 v0 = *(const float4*)(vp), v1 = *(const float4*)(vp + 4);
                    float p = sc[ki];
                    o0.x += p * v0.x; o0.y += p * v0.y; o0.z += p * v0.z; o0.w += p * v0.w;
                    o1.x += p * v1.x; o1.y += p * v1.y; o1.z += p * v1.z; o1.w += p * v1.w;
                }
                if (lane < 25) {
                    uint32_t ob = ((uint32_t)((g * 32 + lane) * LDA + hh * 8)) * 2;
                    uint4 H, L;
                    H.x = pack_hl(o0.x * inv, o0.y * inv, L.x);
                    H.y = pack_hl(o0.z * inv, o0.w * inv, L.y);
                    H.z = pack_hl(o1.x * inv, o1.y * inv, L.z);
                    H.w = pack_hl(o1.z * inv, o1.w * inv, L.w);
                    *(uint4*)(sm + AH_O + ob) = H;
                    *(uint4*)(sm + AL_O + ob) = L;
                }
            }
        }
        __syncthreads();

        ldb(br, sbase + 4, tid);
        gemm_m<1>(sm, smb, AH_O, AL_O, xs, nullptr, tid);   // x += o @ Wo
        __syncthreads(); stb(sm, br, tid); __syncthreads();

        row_cvt_ln<true>(xs, ln2g + l * 56, ln2b + l * 56, b2 + l * 56, sm, tid);
        __syncthreads();

        #pragma unroll 1
        for (int c = 0; c < 4; c++) {
            ldb(br, sbase + 8 + c, tid);
            gemm_m<2>(sm, smb, AH_O, AL_O, nullptr, b1 + l * 224 + c * 56, tid);
            __syncthreads(); stb(sm, br, tid); __syncthreads();
            int nxt = (c < 3) ? (sbase + 5 + c) : ((l < 3) ? (sbase + 12) : 0);
            ldb(br, nxt, tid);
            gemm_m<1>(sm, smb, A2H_O, A2L_O, xs, nullptr, tid);
            __syncthreads(); stb(sm, br, tid); __syncthreads();
        }
    }

    if (tid < 80) {
        int g = tid / 40, r = tid % 40, s = r / 8, i = r % 8;
        long Bi = (long)bx * 2 + g;
        if (Bi < Btot) out[(Bi * 5 + s) * 8 + i] = xs[(g * 32 + s) * LDF + 8 + i];
    }
}

extern "C" void kernel_launch(void* const* d_in, const int* in_sizes, int n_in,
                              void* d_out, int out_size) {
    int o = (n_in >= 20) ? 4 : 3;
    const float* nodes = (const float*)d_in[0];
    const float* edges = (const float*)d_in[1];
    const float* mask  = (const float*)d_in[2];
    const float* W_in  = (const float*)d_in[o + 0];
    const float* b_in  = (const float*)d_in[o + 1];
    const float* W_gp  = (const float*)d_in[o + 2];
    const float* b_gp  = (const float*)d_in[o + 3];
    const float* Wq    = (const float*)d_in[o + 4];
    const float* Wk    = (const float*)d_in[o + 5];
    const float* Wv    = (const float*)d_in[o + 6];
    const float* Wo    = (const float*)d_in[o + 7];
    const float* ln1g  = (const float*)d_in[o + 8];
    const float* ln1b  = (const float*)d_in[o + 9];
    const float* ln2g  = (const float*)d_in[o + 10];
    const float* ln2b  = (const float*)d_in[o + 11];
    const float* W1    = (const float*)d_in[o + 12];
    const float* b1    = (const float*)d_in[o + 13];
    const float* W2    = (const float*)d_in[o + 14];
    const float* b2    = (const float*)d_in[o + 15];

    int B = in_sizes[0] / 120;
    prep_weights<<<48, 256>>>(Wq, Wk, Wv, Wo, W1, W2);
    cudaFuncSetAttribute(nbody_tc, cudaFuncAttributeMaxDynamicSharedMemorySize, SMEMB);
    nbody_tc<<<(B + 1) / 2, 256, SMEMB>>>(nodes, edges, mask, W_in, b_in, W_gp, b_gp,
                                          ln1g, ln1b, ln2g, ln2b, b1, b2, (float*)d_out, B);
}

// round 12
// speedup vs baseline: 1.7198x; 1.1244x over previous
#include <cuda_runtime.h>
#include <cuda_bf16.h>
#include <cstdint>

#define LDF 68
#define LDA 72
#define XS_O 0u
#define QS_O 17408u
#define KS_O 34816u
#define VS_O 52224u
#define AH_O 69632u       // bf16 A hi [64][72] (9216 B)
#define B0H_O 78848u      // B0 hi 9216 + lo 9216
#define B1H_O 97280u      // B1 hi + lo
#define BLO 9216u
#define SMEMB 115712u
#define A2H_O QS_O        // gelu output aliases qs scratch

__device__ uint32_t g_wblob[48 * 4608];   // per stage: 2304 hi + 2304 lo u32

__device__ __forceinline__ float fast_tanh(float x) { float r; asm("tanh.approx.f32 %0, %1;" : "=f"(r) : "f"(x)); return r; }
__device__ __forceinline__ float gelu_t(float x) {
    float t = fast_tanh(0.7978845608028654f * (x + 0.044715f * x * x * x));
    return 0.5f * x * (1.0f + t);
}
__device__ __forceinline__ uint32_t pack_hl(float v0, float v1, uint32_t& lo) {
    __nv_bfloat16 h0 = __float2bfloat16(v0), h1 = __float2bfloat16(v1);
    __nv_bfloat16 l0 = __float2bfloat16(v0 - __bfloat162float(h0));
    __nv_bfloat16 l1 = __float2bfloat16(v1 - __bfloat162float(h1));
    lo = (uint32_t)__bfloat16_as_ushort(l0) | ((uint32_t)__bfloat16_as_ushort(l1) << 16);
    return (uint32_t)__bfloat16_as_ushort(h0) | ((uint32_t)__bfloat16_as_ushort(h1) << 16);
}
__device__ __forceinline__ uint32_t pk2(float v0, float v1) {
    __nv_bfloat16 h0 = __float2bfloat16(v0), h1 = __float2bfloat16(v1);
    return (uint32_t)__bfloat16_as_ushort(h0) | ((uint32_t)__bfloat16_as_ushort(h1) << 16);
}
__device__ __forceinline__ void ldmx4(uint32_t& r0, uint32_t& r1, uint32_t& r2, uint32_t& r3, uint32_t a) {
    asm volatile("ldmatrix.sync.aligned.m8n8.x4.shared.b16 {%0,%1,%2,%3}, [%4];"
        : "=r"(r0), "=r"(r1), "=r"(r2), "=r"(r3) : "r"(a));
}
__device__ __forceinline__ void ldmx4t(uint32_t& r0, uint32_t& r1, uint32_t& r2, uint32_t& r3, uint32_t a) {
    asm volatile("ldmatrix.sync.aligned.m8n8.x4.trans.shared.b16 {%0,%1,%2,%3}, [%4];"
        : "=r"(r0), "=r"(r1), "=r"(r2), "=r"(r3) : "r"(a));
}
__device__ __forceinline__ void mma16816(float (&c)[4], uint32_t a0, uint32_t a1, uint32_t a2, uint32_t a3,
                                         uint32_t b0, uint32_t b1) {
    asm volatile("mma.sync.aligned.m16n8k16.row.col.f32.bf16.bf16.f32 "
        "{%0,%1,%2,%3}, {%4,%5,%6,%7}, {%8,%9}, {%0,%1,%2,%3};"
        : "+f"(c[0]), "+f"(c[1]), "+f"(c[2]), "+f"(c[3])
        : "r"(a0), "r"(a1), "r"(a2), "r"(a3), "r"(b0), "r"(b1));
}

__global__ void prep_weights(const float* __restrict__ Wq, const float* __restrict__ Wk,
                             const float* __restrict__ Wv, const float* __restrict__ Wo,
                             const float* __restrict__ W1, const float* __restrict__ W2) {
    int s = blockIdx.x, l = s / 12, r = s % 12;
    for (int idx = threadIdx.x; idx < 2304; idx += blockDim.x) {
        int k = idx / 36, n2 = idx % 36;
        float vv[2];
        #pragma unroll
        for (int t = 0; t < 2; t++) {
            int c = 2 * n2 + t;
            float v = 0.f;
            if (r < 3) {
                const float* src = (r == 0 ? Wq : (r == 1 ? Wk : Wv)) + l * 3136;
                int hd = c >> 3, di = c & 7;
                if (k < 56 && c < 64 && di < 7) v = src[k * 56 + hd * 7 + di];
            } else if (r == 3) {
                const float* src = Wo + l * 3136;
                int hk = k >> 3, ki = k & 7;
                if (c < 56 && k < 64 && ki < 7) v = src[(hk * 7 + ki) * 56 + c];
            } else if (r < 8) {
                const float* src = W1 + l * 12544;
                if (k < 56 && c < 56) v = src[k * 224 + (r - 4) * 56 + c];
            } else {
                const float* src = W2 + l * 12544;
                if (k < 56 && c < 56) v = src[((r - 8) * 56 + k) * 56 + c];
            }
            vv[t] = v;
        }
        uint32_t lo, hi = pack_hl(vv[0], vv[1], lo);
        g_wblob[s * 4608 + idx] = hi;
        g_wblob[s * 4608 + 2304 + idx] = lo;
    }
}

struct BR { uint4 a, b, c, d, e; };
__device__ __forceinline__ void ldb(BR& br, int s, int tid) {
    const uint4* p = (const uint4*)(g_wblob + s * 4608);
    br.a = __ldg(p + tid);       br.b = __ldg(p + tid + 256);
    br.c = __ldg(p + tid + 512); br.d = __ldg(p + tid + 768);
    if (tid < 128) br.e = __ldg(p + tid + 1024);
}
__device__ __forceinline__ void stb(char* sm, const BR& br, int tid, uint32_t bO) {
    uint4* d = (uint4*)(sm + bO);
    d[tid] = br.a; d[tid + 256] = br.b; d[tid + 512] = br.c; d[tid + 768] = br.d;
    if (tid < 128) d[tid + 1024] = br.e;
}

// GEMM D[64][64] = A_hi[64][64] @ (Bh+Bl)[64][64]; MODE: 0 store, 1 +=, 2 gelu(+bias)->A2 (hi only)
template <int MODE>
__device__ __forceinline__ void gemm_m(char* sm, uint32_t smb, uint32_t aO, uint32_t bO,
                                       float* __restrict__ Dbuf, const float* __restrict__ bias, int tid) {
    const int lane = tid & 31, warp = tid >> 5;
    const int mt = warp >> 1, nh = warp & 1;
    float c[4][4];
    #pragma unroll
    for (int j = 0; j < 4; j++) { c[j][0] = c[j][1] = c[j][2] = c[j][3] = 0.f; }

    uint32_t aoff = ((uint32_t)(mt * 16 + (lane & 15)) * LDA + 8 * (lane >> 4)) * 2;
    uint32_t ahA = smb + aO + aoff;
    int bg = lane >> 3, bi = lane & 7;
    uint32_t boff0 = ((uint32_t)((bg & 1) * 8 + bi) * LDA + nh * 32 + (bg >> 1) * 8) * 2;
    uint32_t bhA = smb + bO + boff0, blA = smb + bO + BLO + boff0;

    #pragma unroll
    for (int ks = 0; ks < 4; ks++) {
        uint32_t kb = ks * 32;
        uint32_t kr = ks * (16 * LDA * 2);
        uint32_t a0, a1, a2, a3;
        ldmx4(a0, a1, a2, a3, ahA + kb);
        uint32_t bh[8], bl[8];
        ldmx4t(bh[0], bh[1], bh[2], bh[3], bhA + kr);
        ldmx4t(bh[4], bh[5], bh[6], bh[7], bhA + kr + 32);
        ldmx4t(bl[0], bl[1], bl[2], bl[3], blA + kr);
        ldmx4t(bl[4], bl[5], bl[6], bl[7], blA + kr + 32);
        #pragma unroll
        for (int j = 0; j < 4; j++) {
            mma16816(c[j], a0, a1, a2, a3, bh[2 * j], bh[2 * j + 1]);
            mma16816(c[j], a0, a1, a2, a3, bl[2 * j], bl[2 * j + 1]);
        }
    }

    const int r0 = mt * 16 + (lane >> 2);
    const int cq = (lane & 3) * 2;
    #pragma unroll
    for (int j = 0; j < 4; j++) {
        int col = nh * 32 + j * 8 + cq;
        if (MODE == 0) {
            *(float2*)(Dbuf + r0 * LDF + col)       = make_float2(c[j][0], c[j][1]);
            *(float2*)(Dbuf + (r0 + 8) * LDF + col) = make_float2(c[j][2], c[j][3]);
        } else if (MODE == 1) {
            float2 p0 = *(float2*)(Dbuf + r0 * LDF + col);
            float2 p1 = *(float2*)(Dbuf + (r0 + 8) * LDF + col);
            p0.x += c[j][0]; p0.y += c[j][1]; p1.x += c[j][2]; p1.y += c[j][3];
            *(float2*)(Dbuf + r0 * LDF + col)       = p0;
            *(float2*)(Dbuf + (r0 + 8) * LDF + col) = p1;
        } else {
            uint32_t h0 = 0, h1 = 0;
            if (!(nh == 1 && j == 3)) {
                float b0 = __ldg(bias + col), b1 = __ldg(bias + col + 1);
                h0 = pk2(gelu_t(c[j][0] + b0), gelu_t(c[j][1] + b1));
                h1 = pk2(gelu_t(c[j][2] + b0), gelu_t(c[j][3] + b1));
            }
            uint32_t o0 = ((uint32_t)(r0 * LDA + col)) * 2, o1 = ((uint32_t)((r0 + 8) * LDA + col)) * 2;
            *(uint32_t*)(sm + A2H_O + o0) = h0;
            *(uint32_t*)(sm + A2H_O + o1) = h1;
        }
    }
}

template <bool ADDB>
__device__ __forceinline__ void row_cvt_ln(float* __restrict__ xs, const float* __restrict__ g,
                                           const float* __restrict__ b, const float* __restrict__ b2,
                                           char* sm, int tid) {
    int r = tid >> 2, part = tid & 3;
    float* xr = xs + r * LDF + part * 14;
    float v[14];
    #pragma unroll
    for (int j = 0; j < 7; j++) *(float2*)(v + 2 * j) = *(const float2*)(xr + 2 * j);
    float s = 0.f, ss = 0.f;
    #pragma unroll
    for (int j = 0; j < 14; j++) { s += v[j]; ss += v[j] * v[j]; }
    s  += __shfl_xor_sync(0xffffffffu, s, 1);
    ss += __shfl_xor_sync(0xffffffffu, ss, 1);
    s  += __shfl_xor_sync(0xffffffffu, s, 2);
    ss += __shfl_xor_sync(0xffffffffu, ss, 2);
    if (ADDB) {
        #pragma unroll
        for (int j = 0; j < 14; j++) xr[j] = v[j] + __ldg(b2 + part * 14 + j);
    }
    float m = s * (1.f / 56.f), rs = rsqrtf(ss * (1.f / 56.f) - m * m + 1e-5f);
    uint32_t* ah = (uint32_t*)(sm + AH_O + ((uint32_t)(r * LDA + part * 14)) * 2);
    #pragma unroll
    for (int t = 0; t < 7; t++) {
        int cl = part * 14 + 2 * t;
        float v0 = (v[2 * t]     - m) * rs * __ldg(g + cl)     + __ldg(b + cl);
        float v1 = (v[2 * t + 1] - m) * rs * __ldg(g + cl + 1) + __ldg(b + cl + 1);
        ah[t] = pk2(v0, v1);
    }
}

__global__ void __launch_bounds__(256, 2)
nbody_tc(const float* __restrict__ nodes, const float* __restrict__ edges,
         const float* __restrict__ mask,
         const float* __restrict__ W_in, const float* __restrict__ b_in,
         const float* __restrict__ W_gp, const float* __restrict__ b_gp,
         const float* __restrict__ ln1g, const float* __restrict__ ln1b,
         const float* __restrict__ ln2g, const float* __restrict__ ln2b,
         const float* __restrict__ b1, const float* __restrict__ b2,
         float* __restrict__ out, int Btot) {
    extern __shared__ char sm[];
    const int tid = threadIdx.x, bx = blockIdx.x;
    const uint32_t smb = (uint32_t)__cvta_generic_to_shared(sm);
    float* xs = (float*)(sm + XS_O);
    float* qs = (float*)(sm + QS_O);
    float* ks = (float*)(sm + KS_O);
    float* vs = (float*)(sm + VS_O);
    BR br;
    ldb(br, 0, tid);                        // Wq(l=0)

    #pragma unroll 1
    for (int i = tid; i < 64 * LDF / 4; i += 256) ((float4*)xs)[i] = make_float4(0.f, 0.f, 0.f, 0.f);
    if (tid < 64)                           // zero A-hi K-pad cols 56..63
        *(uint4*)(sm + AH_O + ((uint32_t)(tid * LDA + 56)) * 2) = make_uint4(0u, 0u, 0u, 0u);

    if (tid < 50) {
        int g = tid / 25, s = tid % 25;
        long Bi = (long)bx * 2 + g;
        if (Bi < Btot) {
            const float* sp = (s < 5) ? nodes + (Bi * 5 + s) * 24 : edges + (Bi * 20 + (s - 5)) * 24;
            float xin[24];
            #pragma unroll
            for (int i = 0; i < 24; i++) xin[i] = __ldg(sp + i);
            const int GR[8] = {0, 1, 1, 1, 2, 2, 2, 3};
            const int POS[8] = {0, 1, 2, 4, 3, 5, 6, 7};
            float* xrow = xs + (g * 32 + s) * LDF;
            #pragma unroll 1
            for (int n = 0; n < 7; n++) {
                float acc[8];
                #pragma unroll
                for (int i = 0; i < 8; i++) acc[i] = (i == 0) ? __ldg(b_gp + n) : 0.f;
                #pragma unroll 1
                for (int m = 0; m < 7; m++) {
                    float mv[8];
                    #pragma unroll
                    for (int i = 0; i < 8; i++) {
                        int gr = GR[i];
                        mv[i] = xin[i] * __ldg(W_in + m * 12 + gr) + xin[8 + i] * __ldg(W_in + m * 12 + 4 + gr)
                              + xin[16 + i] * __ldg(W_in + m * 12 + 8 + gr);
                    }
                    mv[0] += __ldg(b_in + m);
                    float gp[8];
                    #pragma unroll
                    for (int j = 0; j < 8; j++) gp[j] = 0.f;
                    #pragma unroll
                    for (int a = 0; a < 8; a++)
                        #pragma unroll
                        for (int bb = 0; bb < 8; bb++) {
                            int sc = 0;
                            #pragma unroll
                            for (int t = a >> 1; t; t >>= 1) sc += __popc(t & bb);
                            gp[POS[a ^ bb]] += ((sc & 1) ? -1.f : 1.f) * mv[POS[a]] * mv[POS[bb]];
                        }
                    #pragma unroll
                    for (int i = 0; i < 8; i++) {
                        int gr = GR[i];
                        acc[i] += mv[i] * __ldg(W_gp + n * 56 + m * 4 + gr)
                                + gp[i] * __ldg(W_gp + n * 56 + (m + 7) * 4 + gr);
                    }
                }
                #pragma unroll
                for (int i = 0; i < 8; i++) xrow[n * 8 + i] = acc[i];
            }
        }
    }
    __syncthreads();
    stb(sm, br, tid, B0H_O);   // B0 <- Wq(l=0)
    ldb(br, 1, tid);           // br <- Wk(l=0)
    __syncthreads();

    #pragma unroll 1
    for (int l = 0; l < 4; l++) {
        const int sbase = l * 12;
        const int nl = (l < 3) ? (sbase + 12) : 0;
        row_cvt_ln<false>(xs, ln1g + l * 56, ln1b + l * 56, nullptr, sm, tid);
        __syncthreads();

        // Q on B0 | stage B1<-Wk, fetch Wv
        stb(sm, br, tid, B1H_O); ldb(br, sbase + 2, tid);
        gemm_m<0>(sm, smb, AH_O, B0H_O, qs, nullptr, tid);
        __syncthreads();
        // K on B1 | stage B0<-Wv, fetch Wo
        stb(sm, br, tid, B0H_O); ldb(br, sbase + 3, tid);
        gemm_m<0>(sm, smb, AH_O, B1H_O, ks, nullptr, tid);
        __syncthreads();
        // V on B0 | stage B1<-Wo, fetch W1_0
        stb(sm, br, tid, B1H_O); ldb(br, sbase + 4, tid);
        gemm_m<0>(sm, smb, AH_O, B0H_O, vs, nullptr, tid);
        __syncthreads();

        // broadcast attention: warp = (g, head), lane = query s
        {
            int lane = tid & 31, w = tid >> 5;
            #pragma unroll
            for (int rep = 0; rep < 2; rep++) {
                int pair = w + rep * 8;
                int g = pair >> 3, hh = pair & 7;
                long Bi = (long)bx * 2 + g;
                long Bic = (Bi < Btot) ? Bi : (long)(Btot - 1);
                int s = (lane < 25) ? lane : 24;
                int rq = (g * 32 + s) * LDF + hh * 8;
                float4 q0 = *(const float4*)(qs + rq), q1 = *(const float4*)(qs + rq + 4);
                const float* mrow = mask + (Bic * 25 + s) * 25;
                float sc[25]; float mx = -1e30f;
                #pragma unroll
                for (int ki = 0; ki < 25; ki++) {
                    const float* kp = ks + (g * 32 + ki) * LDF + hh * 8;
                    float4 k0 = *(const float4*)(kp), k1 = *(const float4*)(kp + 4);
                    float dot = q0.x * k0.x + q0.y * k0.y + q0.z * k0.z + q0.w * k0.w
                              + q1.x * k1.x + q1.y * k1.y + q1.z * k1.z + q1.w * k1.w;
                    sc[ki] = dot * 0.3779644730092272f + __ldg(mrow + ki);
                    mx = fmaxf(mx, sc[ki]);
                }
                float sum = 0.f;
                #pragma unroll
                for (int ki = 0; ki < 25; ki++) { float e = __expf(sc[ki] - mx); sc[ki] = e; sum += e; }
                float inv = 1.f / sum;
                float4 o0 = make_float4(0.f, 0.f, 0.f, 0.f), o1 = o0;
                #pragma unroll
                for (int ki = 0; ki < 25; ki++) {
                    const float* vp = vs + (g * 32 + ki) * LDF + hh * 8;
                    float4 v0 = *(const float4*)(vp), v1 = *(const float4*)(vp + 4);
                    float p = sc[ki];
                    o0.x += p * v0.x; o0.y += p * v0.y; o0.z += p * v0.z; o0.w += p * v0.w;
                    o1.x += p * v1.x; o1.y += p * v1.y; o1.z += p * v1.z; o1.w += p * v1.w;
                }
                if (lane < 25) {
                    uint32_t ob = ((uint32_t)((g * 32 + lane) * LDA + hh * 8)) * 2;
                    uint4 H;
                    H.x = pk2(o0.x * inv, o0.y * inv);
                    H.y = pk2(o0.z * inv, o0.w * inv);
                    H.z = pk2(o1.x * inv, o1.y * inv);
                    H.w = pk2(o1.z * inv, o1.w * inv);
                    *(uint4*)(sm + AH_O + ob) = H;
                }
            }
        }
        __syncthreads();

        // x += o @ Wo on B1 | stage B0<-W1_0, fetch W2_0
        stb(sm, br, tid, B0H_O); ldb(br, sbase + 8, tid);
        gemm_m<1>(sm, smb, AH_O, B1H_O, xs, nullptr, tid);
        __syncthreads();

        row_cvt_ln<true>(xs, ln2g + l * 56, ln2b + l * 56, b2 + l * 56, sm, tid);
        __syncthreads();

        #pragma unroll 1
        for (int c = 0; c < 4; c++) {
            // W1_c on B0 | stage B1<-W2_c, fetch W1_{c+1} (or next-layer Wq)
            stb(sm, br, tid, B1H_O);
            ldb(br, (c < 3) ? (sbase + 5 + c) : nl, tid);
            gemm_m<2>(sm, smb, AH_O, B0H_O, nullptr, b1 + l * 224 + c * 56, tid);
            __syncthreads();
            // W2_c on B1 | stage B0<-W1_{c+1}/Wq_next, fetch W2_{c+1} (or next-layer Wk)
            stb(sm, br, tid, B0H_O);
            ldb(br, (c < 3) ? (sbase + 9 + c) : (nl + 1), tid);
            gemm_m<1>(sm, smb, A2H_O, B1H_O, xs, nullptr, tid);
            __syncthreads();
        }
    }

    if (tid < 80) {
        int g = tid / 40, r = tid % 40, s = r / 8, i = r % 8;
        long Bi = (long)bx * 2 + g;
        if (Bi < Btot) out[(Bi * 5 + s) * 8 + i] = xs[(g * 32 + s) * LDF + 8 + i];
    }
}

extern "C" void kernel_launch(void* const* d_in, const int* in_sizes, int n_in,
                              void* d_out, int out_size) {
    int o = (n_in >= 20) ? 4 : 3;
    const float* nodes = (const float*)d_in[0];
    const float* edges = (const float*)d_in[1];
    const float* mask  = (const float*)d_in[2];
    const float* W_in  = (const float*)d_in[o + 0];
    const float* b_in  = (const float*)d_in[o + 1];
    const float* W_gp  = (const float*)d_in[o + 2];
    const float* b_gp  = (const float*)d_in[o + 3];
    const float* Wq    = (const float*)d_in[o + 4];
    const float* Wk    = (const float*)d_in[o + 5];
    const float* Wv    = (const float*)d_in[o + 6];
    const float* Wo    = (const float*)d_in[o + 7];
    const float* ln1g  = (const float*)d_in[o + 8];
    const float* ln1b  = (const float*)d_in[o + 9];
    const float* ln2g  = (const float*)d_in[o + 10];
    const float* ln2b  = (const float*)d_in[o + 11];
    const float* W1    = (const float*)d_in[o + 12];
    const float* b1    = (const float*)d_in[o + 13];
    const float* W2    = (const float*)d_in[o + 14];
    const float* b2    = (const float*)d_in[o + 15];

    int B = in_sizes[0] / 120;
    prep_weights<<<48, 256>>>(Wq, Wk, Wv, Wo, W1, W2);
    cudaFuncSetAttribute(nbody_tc, cudaFuncAttributeMaxDynamicSharedMemorySize, SMEMB);
    nbody_tc<<<(B + 1) / 2, 256, SMEMB>>>(nodes, edges, mask, W_in, b_in, W_gp, b_gp,
                                          ln1g, ln1b, ln2g, ln2b, b1, b2, (float*)d_out, B);
}

// round 13
// speedup vs baseline: 1.7720x; 1.0304x over previous
#include <cuda_runtime.h>
#include <cuda_bf16.h>
#include <cstdint>

#define LDF 68
#define LDA 72
#define XS_O 0u
#define QS_O 17408u
#define KS_O 34816u
#define VS_O 52224u
#define AH_O 69632u       // bf16 A hi [64][72] (9216 B)
#define B0H_O 78848u      // B0 hi 9216 + lo 9216
#define B1H_O 97280u      // B1 hi + lo
#define BLO 9216u
#define SMEMB 115712u
#define A2H_O QS_O        // gelu output aliases qs scratch

__device__ uint32_t g_wblob[48 * 4608];   // per stage: 2304 hi + 2304 lo u32

__device__ __forceinline__ float fast_tanh(float x) { float r; asm("tanh.approx.f32 %0, %1;" : "=f"(r) : "f"(x)); return r; }
__device__ __forceinline__ float gelu_t(float x) {
    float t = fast_tanh(0.7978845608028654f * (x + 0.044715f * x * x * x));
    return 0.5f * x * (1.0f + t);
}
__device__ __forceinline__ uint32_t pack_hl(float v0, float v1, uint32_t& lo) {
    __nv_bfloat16 h0 = __float2bfloat16(v0), h1 = __float2bfloat16(v1);
    __nv_bfloat16 l0 = __float2bfloat16(v0 - __bfloat162float(h0));
    __nv_bfloat16 l1 = __float2bfloat16(v1 - __bfloat162float(h1));
    lo = (uint32_t)__bfloat16_as_ushort(l0) | ((uint32_t)__bfloat16_as_ushort(l1) << 16);
    return (uint32_t)__bfloat16_as_ushort(h0) | ((uint32_t)__bfloat16_as_ushort(h1) << 16);
}
__device__ __forceinline__ uint32_t pk2(float v0, float v1) {
    __nv_bfloat16 h0 = __float2bfloat16(v0), h1 = __float2bfloat16(v1);
    return (uint32_t)__bfloat16_as_ushort(h0) | ((uint32_t)__bfloat16_as_ushort(h1) << 16);
}
__device__ __forceinline__ void ldmx4(uint32_t& r0, uint32_t& r1, uint32_t& r2, uint32_t& r3, uint32_t a) {
    asm volatile("ldmatrix.sync.aligned.m8n8.x4.shared.b16 {%0,%1,%2,%3}, [%4];"
        : "=r"(r0), "=r"(r1), "=r"(r2), "=r"(r3) : "r"(a));
}
__device__ __forceinline__ void ldmx4t(uint32_t& r0, uint32_t& r1, uint32_t& r2, uint32_t& r3, uint32_t a) {
    asm volatile("ldmatrix.sync.aligned.m8n8.x4.trans.shared.b16 {%0,%1,%2,%3}, [%4];"
        : "=r"(r0), "=r"(r1), "=r"(r2), "=r"(r3) : "r"(a));
}
__device__ __forceinline__ void mma16816(float (&c)[4], uint32_t a0, uint32_t a1, uint32_t a2, uint32_t a3,
                                         uint32_t b0, uint32_t b1) {
    asm volatile("mma.sync.aligned.m16n8k16.row.col.f32.bf16.bf16.f32 "
        "{%0,%1,%2,%3}, {%4,%5,%6,%7}, {%8,%9}, {%0,%1,%2,%3};"
        : "+f"(c[0]), "+f"(c[1]), "+f"(c[2]), "+f"(c[3])
        : "r"(a0), "r"(a1), "r"(a2), "r"(a3), "r"(b0), "r"(b1));
}

__global__ void prep_weights(const float* __restrict__ Wq, const float* __restrict__ Wk,
                             const float* __restrict__ Wv, const float* __restrict__ Wo,
                             const float* __restrict__ W1, const float* __restrict__ W2) {
    int s = blockIdx.x, l = s / 12, r = s % 12;
    for (int idx = threadIdx.x; idx < 2304; idx += blockDim.x) {
        int k = idx / 36, n2 = idx % 36;
        float vv[2];
        #pragma unroll
        for (int t = 0; t < 2; t++) {
            int c = 2 * n2 + t;
            float v = 0.f;
            if (r < 3) {
                const float* src = (r == 0 ? Wq : (r == 1 ? Wk : Wv)) + l * 3136;
                int hd = c >> 3, di = c & 7;
                if (k < 56 && c < 64 && di < 7) v = src[k * 56 + hd * 7 + di];
            } else if (r == 3) {
                const float* src = Wo + l * 3136;
                int hk = k >> 3, ki = k & 7;
                if (c < 56 && k < 64 && ki < 7) v = src[(hk * 7 + ki) * 56 + c];
            } else if (r < 8) {
                const float* src = W1 + l * 12544;
                if (k < 56 && c < 56) v = src[k * 224 + (r - 4) * 56 + c];
            } else {
                const float* src = W2 + l * 12544;
                if (k < 56 && c < 56) v = src[((r - 8) * 56 + k) * 56 + c];
            }
            vv[t] = v;
        }
        uint32_t lo, hi = pack_hl(vv[0], vv[1], lo);
        g_wblob[s * 4608 + idx] = hi;
        g_wblob[s * 4608 + 2304 + idx] = lo;
    }
}

struct BR { uint4 a, b, c, d, e; };
__device__ __forceinline__ void ldb(BR& br, int s, int tid) {
    const uint4* p = (const uint4*)(g_wblob + s * 4608);
    br.a = __ldg(p + tid);       br.b = __ldg(p + tid + 256);
    br.c = __ldg(p + tid + 512); br.d = __ldg(p + tid + 768);
    if (tid < 128) br.e = __ldg(p + tid + 1024);
}
__device__ __forceinline__ void stb(char* sm, const BR& br, int tid, uint32_t bO) {
    uint4* d = (uint4*)(sm + bO);
    d[tid] = br.a; d[tid + 256] = br.b; d[tid + 512] = br.c; d[tid + 768] = br.d;
    if (tid < 128) d[tid + 1024] = br.e;
}

// GEMM D[64][64] = A_hi[64][64] @ (Bh+Bl)[64][64]
// warp tile 32 rows x 16 cols: mt = warp>>2 (0..1), nq = warp&3 (0..3)
// MODE: 0 store, 1 +=, 2 gelu(+bias)->A2 (hi only)
template <int MODE>
__device__ __forceinline__ void gemm_m(char* sm, uint32_t smb, uint32_t aO, uint32_t bO,
                                       float* __restrict__ Dbuf, const float* __restrict__ bias, int tid) {
    const int lane = tid & 31, warp = tid >> 5;
    const int mt = warp >> 2, nq = warp & 3;
    float c[2][2][4];
    #pragma unroll
    for (int s = 0; s < 2; s++)
        #pragma unroll
        for (int j = 0; j < 2; j++) { c[s][j][0] = c[s][j][1] = c[s][j][2] = c[s][j][3] = 0.f; }

    uint32_t a0off = ((uint32_t)(mt * 32 + (lane & 15)) * LDA + 8 * (lane >> 4)) * 2;
    uint32_t a1off = ((uint32_t)(mt * 32 + 16 + (lane & 15)) * LDA + 8 * (lane >> 4)) * 2;
    uint32_t ahA0 = smb + aO + a0off, ahA1 = smb + aO + a1off;
    int bg = lane >> 3, bi = lane & 7;
    uint32_t boff0 = ((uint32_t)((bg & 1) * 8 + bi) * LDA + nq * 16 + (bg >> 1) * 8) * 2;
    uint32_t bhA = smb + bO + boff0, blA = smb + bO + BLO + boff0;

    #pragma unroll
    for (int ks = 0; ks < 4; ks++) {
        uint32_t kb = ks * 32;
        uint32_t kr = ks * (16 * LDA * 2);
        uint32_t a0, a1, a2, a3, a4, a5, a6, a7;
        ldmx4(a0, a1, a2, a3, ahA0 + kb);
        ldmx4(a4, a5, a6, a7, ahA1 + kb);
        uint32_t bh[4], bl[4];
        ldmx4t(bh[0], bh[1], bh[2], bh[3], bhA + kr);
        ldmx4t(bl[0], bl[1], bl[2], bl[3], blA + kr);
        #pragma unroll
        for (int j = 0; j < 2; j++) {
            mma16816(c[0][j], a0, a1, a2, a3, bh[2 * j], bh[2 * j + 1]);
            mma16816(c[0][j], a0, a1, a2, a3, bl[2 * j], bl[2 * j + 1]);
            mma16816(c[1][j], a4, a5, a6, a7, bh[2 * j], bh[2 * j + 1]);
            mma16816(c[1][j], a4, a5, a6, a7, bl[2 * j], bl[2 * j + 1]);
        }
    }

    const int cq = (lane & 3) * 2;
    #pragma unroll
    for (int s = 0; s < 2; s++) {
        const int r0 = mt * 32 + s * 16 + (lane >> 2);
        #pragma unroll
        for (int j = 0; j < 2; j++) {
            int col = nq * 16 + j * 8 + cq;
            if (MODE == 0) {
                *(float2*)(Dbuf + r0 * LDF + col)       = make_float2(c[s][j][0], c[s][j][1]);
                *(float2*)(Dbuf + (r0 + 8) * LDF + col) = make_float2(c[s][j][2], c[s][j][3]);
            } else if (MODE == 1) {
                float2 p0 = *(float2*)(Dbuf + r0 * LDF + col);
                float2 p1 = *(float2*)(Dbuf + (r0 + 8) * LDF + col);
                p0.x += c[s][j][0]; p0.y += c[s][j][1]; p1.x += c[s][j][2]; p1.y += c[s][j][3];
                *(float2*)(Dbuf + r0 * LDF + col)       = p0;
                *(float2*)(Dbuf + (r0 + 8) * LDF + col) = p1;
            } else {
                uint32_t h0 = 0, h1 = 0;
                if (!(nq == 3 && j == 1)) {          // cols 56..63 stay zero, no bias OOB
                    float b0 = __ldg(bias + col), b1 = __ldg(bias + col + 1);
                    h0 = pk2(gelu_t(c[s][j][0] + b0), gelu_t(c[s][j][1] + b1));
                    h1 = pk2(gelu_t(c[s][j][2] + b0), gelu_t(c[s][j][3] + b1));
                }
                uint32_t o0 = ((uint32_t)(r0 * LDA + col)) * 2, o1 = ((uint32_t)((r0 + 8) * LDA + col)) * 2;
                *(uint32_t*)(sm + A2H_O + o0) = h0;
                *(uint32_t*)(sm + A2H_O + o1) = h1;
            }
        }
    }
}

template <bool ADDB>
__device__ __forceinline__ void row_cvt_ln(float* __restrict__ xs, const float* __restrict__ g,
                                           const float* __restrict__ b, const float* __restrict__ b2,
                                           char* sm, int tid) {
    int r = tid >> 2, part = tid & 3;
    float* xr = xs + r * LDF + part * 14;
    float v[14];
    #pragma unroll
    for (int j = 0; j < 7; j++) *(float2*)(v + 2 * j) = *(const float2*)(xr + 2 * j);
    float s = 0.f, ss = 0.f;
    #pragma unroll
    for (int j = 0; j < 14; j++) { s += v[j]; ss += v[j] * v[j]; }
    s  += __shfl_xor_sync(0xffffffffu, s, 1);
    ss += __shfl_xor_sync(0xffffffffu, ss, 1);
    s  += __shfl_xor_sync(0xffffffffu, s, 2);
    ss += __shfl_xor_sync(0xffffffffu, ss, 2);
    if (ADDB) {
        #pragma unroll
        for (int j = 0; j < 14; j++) xr[j] = v[j] + __ldg(b2 + part * 14 + j);
    }
    float m = s * (1.f / 56.f), rs = rsqrtf(ss * (1.f / 56.f) - m * m + 1e-5f);
    uint32_t* ah = (uint32_t*)(sm + AH_O + ((uint32_t)(r * LDA + part * 14)) * 2);
    #pragma unroll
    for (int t = 0; t < 7; t++) {
        int cl = part * 14 + 2 * t;
        float v0 = (v[2 * t]     - m) * rs * __ldg(g + cl)     + __ldg(b + cl);
        float v1 = (v[2 * t + 1] - m) * rs * __ldg(g + cl + 1) + __ldg(b + cl + 1);
        ah[t] = pk2(v0, v1);
    }
}

__global__ void __launch_bounds__(256, 2)
nbody_tc(const float* __restrict__ nodes, const float* __restrict__ edges,
         const float* __restrict__ mask,
         const float* __restrict__ W_in, const float* __restrict__ b_in,
         const float* __restrict__ W_gp, const float* __restrict__ b_gp,
         const float* __restrict__ ln1g, const float* __restrict__ ln1b,
         const float* __restrict__ ln2g, const float* __restrict__ ln2b,
         const float* __restrict__ b1, const float* __restrict__ b2,
         float* __restrict__ out, int Btot) {
    extern __shared__ char sm[];
    const int tid = threadIdx.x, bx = blockIdx.x;
    const uint32_t smb = (uint32_t)__cvta_generic_to_shared(sm);
    float* xs = (float*)(sm + XS_O);
    float* qs = (float*)(sm + QS_O);
    float* ks = (float*)(sm + KS_O);
    float* vs = (float*)(sm + VS_O);
    BR br;
    ldb(br, 0, tid);                        // Wq(l=0)

    #pragma unroll 1
    for (int i = tid; i < 64 * LDF / 4; i += 256) ((float4*)xs)[i] = make_float4(0.f, 0.f, 0.f, 0.f);
    if (tid < 64)                           // zero A-hi K-pad cols 56..63
        *(uint4*)(sm + AH_O + ((uint32_t)(tid * LDA + 56)) * 2) = make_uint4(0u, 0u, 0u, 0u);

    if (tid < 50) {
        int g = tid / 25, s = tid % 25;
        long Bi = (long)bx * 2 + g;
        if (Bi < Btot) {
            const float* sp = (s < 5) ? nodes + (Bi * 5 + s) * 24 : edges + (Bi * 20 + (s - 5)) * 24;
            float xin[24];
            #pragma unroll
            for (int i = 0; i < 24; i++) xin[i] = __ldg(sp + i);
            const int GR[8] = {0, 1, 1, 1, 2, 2, 2, 3};
            const int POS[8] = {0, 1, 2, 4, 3, 5, 6, 7};
            float* xrow = xs + (g * 32 + s) * LDF;
            #pragma unroll 1
            for (int n = 0; n < 7; n++) {
                float acc[8];
                #pragma unroll
                for (int i = 0; i < 8; i++) acc[i] = (i == 0) ? __ldg(b_gp + n) : 0.f;
                #pragma unroll 1
                for (int m = 0; m < 7; m++) {
                    float mv[8];
                    #pragma unroll
                    for (int i = 0; i < 8; i++) {
                        int gr = GR[i];
                        mv[i] = xin[i] * __ldg(W_in + m * 12 + gr) + xin[8 + i] * __ldg(W_in + m * 12 + 4 + gr)
                              + xin[16 + i] * __ldg(W_in + m * 12 + 8 + gr);
                    }
                    mv[0] += __ldg(b_in + m);
                    float gp[8];
                    #pragma unroll
                    for (int j = 0; j < 8; j++) gp[j] = 0.f;
                    #pragma unroll
                    for (int a = 0; a < 8; a++)
                        #pragma unroll
                        for (int bb = 0; bb < 8; bb++) {
                            int sc = 0;
                            #pragma unroll
                            for (int t = a >> 1; t; t >>= 1) sc += __popc(t & bb);
                            gp[POS[a ^ bb]] += ((sc & 1) ? -1.f : 1.f) * mv[POS[a]] * mv[POS[bb]];
                        }
                    #pragma unroll
                    for (int i = 0; i < 8; i++) {
                        int gr = GR[i];
                        acc[i] += mv[i] * __ldg(W_gp + n * 56 + m * 4 + gr)
                                + gp[i] * __ldg(W_gp + n * 56 + (m + 7) * 4 + gr);
                    }
                }
                #pragma unroll
                for (int i = 0; i < 8; i++) xrow[n * 8 + i] = acc[i];
            }
        }
    }
    __syncthreads();
    stb(sm, br, tid, B0H_O);   // B0 <- Wq(l=0)
    ldb(br, 1, tid);           // br <- Wk(l=0)
    __syncthreads();

    #pragma unroll 1
    for (int l = 0; l < 4; l++) {
        const int sbase = l * 12;
        const int nl = (l < 3) ? (sbase + 12) : 0;
        row_cvt_ln<false>(xs, ln1g + l * 56, ln1b + l * 56, nullptr, sm, tid);
        __syncthreads();

        // Q on B0 | stage B1<-Wk, fetch Wv
        stb(sm, br, tid, B1H_O); ldb(br, sbase + 2, tid);
        gemm_m<0>(sm, smb, AH_O, B0H_O, qs, nullptr, tid);
        __syncthreads();
        // K on B1 | stage B0<-Wv, fetch Wo
        stb(sm, br, tid, B0H_O); ldb(br, sbase + 3, tid);
        gemm_m<0>(sm, smb, AH_O, B1H_O, ks, nullptr, tid);
        __syncthreads();
        // V on B0 | stage B1<-Wo, fetch W1_0
        stb(sm, br, tid, B1H_O); ldb(br, sbase + 4, tid);
        gemm_m<0>(sm, smb, AH_O, B0H_O, vs, nullptr, tid);
        __syncthreads();

        // broadcast attention: warp = (g, head), lane = query s
        {
            int lane = tid & 31, w = tid >> 5;
            #pragma unroll
            for (int rep = 0; rep < 2; rep++) {
                int pair = w + rep * 8;
                int g = pair >> 3, hh = pair & 7;
                long Bi = (long)bx * 2 + g;
                long Bic = (Bi < Btot) ? Bi : (long)(Btot - 1);
                int s = (lane < 25) ? lane : 24;
                int rq = (g * 32 + s) * LDF + hh * 8;
                float4 q0 = *(const float4*)(qs + rq), q1 = *(const float4*)(qs + rq + 4);
                const float* mrow = mask + (Bic * 25 + s) * 25;
                float sc[25]; float mx = -1e30f;
                #pragma unroll
                for (int ki = 0; ki < 25; ki++) {
                    const float* kp = ks + (g * 32 + ki) * LDF + hh * 8;
                    float4 k0 = *(const float4*)(kp), k1 = *(const float4*)(kp + 4);
                    float dot = q0.x * k0.x + q0.y * k0.y + q0.z * k0.z + q0.w * k0.w
                              + q1.x * k1.x + q1.y * k1.y + q1.z * k1.z + q1.w * k1.w;
                    sc[ki] = dot * 0.3779644730092272f + __ldg(mrow + ki);
                    mx = fmaxf(mx, sc[ki]);
                }
                float sum = 0.f;
                #pragma unroll
                for (int ki = 0; ki < 25; ki++) { float e = __expf(sc[ki] - mx); sc[ki] = e; sum += e; }
                float inv = 1.f / sum;
                float4 o0 = make_float4(0.f, 0.f, 0.f, 0.f), o1 = o0;
                #pragma unroll
                for (int ki = 0; ki < 25; ki++) {
                    const float* vp = vs + (g * 32 + ki) * LDF + hh * 8;
                    float4 v0 = *(const float4*)(vp), v1 = *(const float4*)(vp + 4);
                    float p = sc[ki];
                    o0.x += p * v0.x; o0.y += p * v0.y; o0.z += p * v0.z; o0.w += p * v0.w;
                    o1.x += p * v1.x; o1.y += p * v1.y; o1.z += p * v1.z; o1.w += p * v1.w;
                }
                if (lane < 25) {
                    uint32_t ob = ((uint32_t)((g * 32 + lane) * LDA + hh * 8)) * 2;
                    uint4 H;
                    H.x = pk2(o0.x * inv, o0.y * inv);
                    H.y = pk2(o0.z * inv, o0.w * inv);
                    H.z = pk2(o1.x * inv, o1.y * inv);
                    H.w = pk2(o1.z * inv, o1.w * inv);
                    *(uint4*)(sm + AH_O + ob) = H;
                }
            }
        }
        __syncthreads();

        // x += o @ Wo on B1 | stage B0<-W1_0, fetch W2_0
        stb(sm, br, tid, B0H_O); ldb(br, sbase + 8, tid);
        gemm_m<1>(sm, smb, AH_O, B1H_O, xs, nullptr, tid);
        __syncthreads();

        row_cvt_ln<true>(xs, ln2g + l * 56, ln2b + l * 56, b2 + l * 56, sm, tid);
        __syncthreads();

        #pragma unroll 1
        for (int c = 0; c < 4; c++) {
            // W1_c on B0 | stage B1<-W2_c, fetch W1_{c+1} (or next-layer Wq)
            stb(sm, br, tid, B1H_O);
            ldb(br, (c < 3) ? (sbase + 5 + c) : nl, tid);
            gemm_m<2>(sm, smb, AH_O, B0H_O, nullptr, b1 + l * 224 + c * 56, tid);
            __syncthreads();
            // W2_c on B1 | stage B0<-W1_{c+1}/Wq_next, fetch W2_{c+1} (or next-layer Wk)
            stb(sm, br, tid, B0H_O);
            ldb(br, (c < 3) ? (sbase + 9 + c) : (nl + 1), tid);
            gemm_m<1>(sm, smb, A2H_O, B1H_O, xs, nullptr, tid);
            __syncthreads();
        }
    }

    if (tid < 80) {
        int g = tid / 40, r = tid % 40, s = r / 8, i = r % 8;
        long Bi = (long)bx * 2 + g;
        if (Bi < Btot) out[(Bi * 5 + s) * 8 + i] = xs[(g * 32 + s) * LDF + 8 + i];
    }
}

extern "C" void kernel_launch(void* const* d_in, const int* in_sizes, int n_in,
                              void* d_out, int out_size) {
    int o = (n_in >= 20) ? 4 : 3;
    const float* nodes = (const float*)d_in[0];
    const float* edges = (const float*)d_in[1];
    const float* mask  = (const float*)d_in[2];
    const float* W_in  = (const float*)d_in[o + 0];
    const float* b_in  = (const float*)d_in[o + 1];
    const float* W_gp  = (const float*)d_in[o + 2];
    const float* b_gp  = (const float*)d_in[o + 3];
    const float* Wq    = (const float*)d_in[o + 4];
    const float* Wk    = (const float*)d_in[o + 5];
    const float* Wv    = (const float*)d_in[o + 6];
    const float* Wo    = (const float*)d_in[o + 7];
    const float* ln1g  = (const float*)d_in[o + 8];
    const float* ln1b  = (const float*)d_in[o + 9];
    const float* ln2g  = (const float*)d_in[o + 10];
    const float* ln2b  = (const float*)d_in[o + 11];
    const float* W1    = (const float*)d_in[o + 12];
    const float* b1    = (const float*)d_in[o + 13];
    const float* W2    = (const float*)d_in[o + 14];
    const float* b2    = (const float*)d_in[o + 15];

    int B = in_sizes[0] / 120;
    prep_weights<<<48, 256>>>(Wq, Wk, Wv, Wo, W1, W2);
    cudaFuncSetAttribute(nbody_tc, cudaFuncAttributeMaxDynamicSharedMemorySize, SMEMB);
    nbody_tc<<<(B + 1) / 2, 256, SMEMB>>>(nodes, edges, mask, W_in, b_in, W_gp, b_gp,
                                          ln1g, ln1b, ln2g, ln2b, b1, b2, (float*)d_out, B);
}

// round 16
// speedup vs baseline: 1.7833x; 1.0064x over previous
#include <cuda_runtime.h>
#include <cuda_bf16.h>
#include <cstdint>

#define LDF 68
#define LDA 72
#define XS_O 0u           // f32 residual [64][68]
#define QS_O 17408u       // bf16 q [64][72] (9216 B)
#define KS_O 26624u
#define VS_O 35840u
#define AH_O 45056u       // bf16 A hi
#define B0H_O 54272u      // B0 hi 9216 + lo 9216
#define B1H_O 72704u
#define BLO 9216u
#define SMEMB 91136u
#define A2H_O QS_O        // gelu output aliases qs (bf16, 9216)

__device__ uint32_t g_wblob[48 * 4608];   // per stage: 2304 hi + 2304 lo u32

__device__ __forceinline__ float fast_tanh(float x) { float r; asm("tanh.approx.f32 %0, %1;" : "=f"(r) : "f"(x)); return r; }
__device__ __forceinline__ float gelu_t(float x) {
    float t = fast_tanh(0.7978845608028654f * (x + 0.044715f * x * x * x));
    return 0.5f * x * (1.0f + t);
}
__device__ __forceinline__ uint32_t pack_hl(float v0, float v1, uint32_t& lo) {
    __nv_bfloat16 h0 = __float2bfloat16(v0), h1 = __float2bfloat16(v1);
    __nv_bfloat16 l0 = __float2bfloat16(v0 - __bfloat162float(h0));
    __nv_bfloat16 l1 = __float2bfloat16(v1 - __bfloat162float(h1));
    lo = (uint32_t)__bfloat16_as_ushort(l0) | ((uint32_t)__bfloat16_as_ushort(l1) << 16);
    return (uint32_t)__bfloat16_as_ushort(h0) | ((uint32_t)__bfloat16_as_ushort(h1) << 16);
}
__device__ __forceinline__ uint32_t pk2(float v0, float v1) {
    __nv_bfloat16 h0 = __float2bfloat16(v0), h1 = __float2bfloat16(v1);
    return (uint32_t)__bfloat16_as_ushort(h0) | ((uint32_t)__bfloat16_as_ushort(h1) << 16);
}
__device__ __forceinline__ float bf_lo(uint32_t u) { return __uint_as_float(u << 16); }
__device__ __forceinline__ float bf_hi(uint32_t u) { return __uint_as_float(u & 0xffff0000u); }
__device__ __forceinline__ void ldmx4(uint32_t& r0, uint32_t& r1, uint32_t& r2, uint32_t& r3, uint32_t a) {
    asm volatile("ldmatrix.sync.aligned.m8n8.x4.shared.b16 {%0,%1,%2,%3}, [%4];"
        : "=r"(r0), "=r"(r1), "=r"(r2), "=r"(r3) : "r"(a));
}
__device__ __forceinline__ void ldmx4t(uint32_t& r0, uint32_t& r1, uint32_t& r2, uint32_t& r3, uint32_t a) {
    asm volatile("ldmatrix.sync.aligned.m8n8.x4.trans.shared.b16 {%0,%1,%2,%3}, [%4];"
        : "=r"(r0), "=r"(r1), "=r"(r2), "=r"(r3) : "r"(a));
}
__device__ __forceinline__ void mma16816(float (&c)[4], uint32_t a0, uint32_t a1, uint32_t a2, uint32_t a3,
                                         uint32_t b0, uint32_t b1) {
    asm volatile("mma.sync.aligned.m16n8k16.row.col.f32.bf16.bf16.f32 "
        "{%0,%1,%2,%3}, {%4,%5,%6,%7}, {%8,%9}, {%0,%1,%2,%3};"
        : "+f"(c[0]), "+f"(c[1]), "+f"(c[2]), "+f"(c[3])
        : "r"(a0), "r"(a1), "r"(a2), "r"(a3), "r"(b0), "r"(b1));
}

__global__ void prep_weights(const float* __restrict__ Wq, const float* __restrict__ Wk,
                             const float* __restrict__ Wv, const float* __restrict__ Wo,
                             const float* __restrict__ W1, const float* __restrict__ W2) {
    int s = blockIdx.x, l = s / 12, r = s % 12;
    for (int idx = threadIdx.x; idx < 2304; idx += blockDim.x) {
        int k = idx / 36, n2 = idx % 36;
        float vv[2];
        #pragma unroll
        for (int t = 0; t < 2; t++) {
            int c = 2 * n2 + t;
            float v = 0.f;
            if (r < 3) {
                const float* src = (r == 0 ? Wq : (r == 1 ? Wk : Wv)) + l * 3136;
                int hd = c >> 3, di = c & 7;
                if (k < 56 && c < 64 && di < 7) v = src[k * 56 + hd * 7 + di];
            } else if (r == 3) {
                const float* src = Wo + l * 3136;
                int hk = k >> 3, ki = k & 7;
                if (c < 56 && k < 64 && ki < 7) v = src[(hk * 7 + ki) * 56 + c];
            } else if (r < 8) {
                const float* src = W1 + l * 12544;
                if (k < 56 && c < 56) v = src[k * 224 + (r - 4) * 56 + c];
            } else {
                const float* src = W2 + l * 12544;
                if (k < 56 && c < 56) v = src[((r - 8) * 56 + k) * 56 + c];
            }
            vv[t] = v;
        }
        uint32_t lo, hi = pack_hl(vv[0], vv[1], lo);
        g_wblob[s * 4608 + idx] = hi;
        g_wblob[s * 4608 + 2304 + idx] = lo;
    }
}

struct BR { uint4 a, b, c, d, e; };
__device__ __forceinline__ void ldb(BR& br, int s, int tid) {
    const uint4* p = (const uint4*)(g_wblob + s * 4608);
    br.a = __ldg(p + tid);       br.b = __ldg(p + tid + 256);
    br.c = __ldg(p + tid + 512); br.d = __ldg(p + tid + 768);
    if (tid < 128) br.e = __ldg(p + tid + 1024);
}
__device__ __forceinline__ void stb(char* sm, const BR& br, int tid, uint32_t bO) {
    uint4* d = (uint4*)(sm + bO);
    d[tid] = br.a; d[tid + 256] = br.b; d[tid + 512] = br.c; d[tid + 768] = br.d;
    if (tid < 128) d[tid + 1024] = br.e;
}

// GEMM D[64][64] = A_hi[64][64] @ (Bh+Bl)[64][64]; warp tile 32x16 (mt=warp>>2, nq=warp&3)
// MODE 0: store bf16 -> sm+dO   1: xs +=   2: gelu(+bias) bf16 -> sm+dO
template <int MODE>
__device__ __forceinline__ void gemm_m(char* sm, uint32_t smb, uint32_t aO, uint32_t bO,
                                       float* __restrict__ Dbuf, uint32_t dO,
                                       const float* __restrict__ bias, int tid) {
    const int lane = tid & 31, warp = tid >> 5;
    const int mt = warp >> 2, nq = warp & 3;
    float c[2][2][4];
    #pragma unroll
    for (int s = 0; s < 2; s++)
        #pragma unroll
        for (int j = 0; j < 2; j++) { c[s][j][0] = c[s][j][1] = c[s][j][2] = c[s][j][3] = 0.f; }

    uint32_t a0off = ((uint32_t)(mt * 32 + (lane & 15)) * LDA + 8 * (lane >> 4)) * 2;
    uint32_t a1off = ((uint32_t)(mt * 32 + 16 + (lane & 15)) * LDA + 8 * (lane >> 4)) * 2;
    uint32_t ahA0 = smb + aO + a0off, ahA1 = smb + aO + a1off;
    int bg = lane >> 3, bi = lane & 7;
    uint32_t boff0 = ((uint32_t)((bg & 1) * 8 + bi) * LDA + nq * 16 + (bg >> 1) * 8) * 2;
    uint32_t bhA = smb + bO + boff0, blA = smb + bO + BLO + boff0;

    #pragma unroll
    for (int ks = 0; ks < 4; ks++) {
        uint32_t kb = ks * 32;
        uint32_t kr = ks * (16 * LDA * 2);
        uint32_t a0, a1, a2, a3, a4, a5, a6, a7;
        ldmx4(a0, a1, a2, a3, ahA0 + kb);
        ldmx4(a4, a5, a6, a7, ahA1 + kb);
        uint32_t bh[4], bl[4];
        ldmx4t(bh[0], bh[1], bh[2], bh[3], bhA + kr);
        ldmx4t(bl[0], bl[1], bl[2], bl[3], blA + kr);
        #pragma unroll
        for (int j = 0; j < 2; j++) {
            mma16816(c[0][j], a0, a1, a2, a3, bh[2 * j], bh[2 * j + 1]);
            mma16816(c[0][j], a0, a1, a2, a3, bl[2 * j], bl[2 * j + 1]);
            mma16816(c[1][j], a4, a5, a6, a7, bh[2 * j], bh[2 * j + 1]);
            mma16816(c[1][j], a4, a5, a6, a7, bl[2 * j], bl[2 * j + 1]);
        }
    }

    const int cq = (lane & 3) * 2;
    #pragma unroll
    for (int s = 0; s < 2; s++) {
        const int r0 = mt * 32 + s * 16 + (lane >> 2);
        #pragma unroll
        for (int j = 0; j < 2; j++) {
            int col = nq * 16 + j * 8 + cq;
            if (MODE == 0) {
                *(uint32_t*)(sm + dO + ((uint32_t)(r0 * LDA + col)) * 2)       = pk2(c[s][j][0], c[s][j][1]);
                *(uint32_t*)(sm + dO + ((uint32_t)((r0 + 8) * LDA + col)) * 2) = pk2(c[s][j][2], c[s][j][3]);
            } else if (MODE == 1) {
                float2 p0 = *(float2*)(Dbuf + r0 * LDF + col);
                float2 p1 = *(float2*)(Dbuf + (r0 + 8) * LDF + col);
                p0.x += c[s][j][0]; p0.y += c[s][j][1]; p1.x += c[s][j][2]; p1.y += c[s][j][3];
                *(float2*)(Dbuf + r0 * LDF + col)       = p0;
                *(float2*)(Dbuf + (r0 + 8) * LDF + col) = p1;
            } else {
                uint32_t h0 = 0, h1 = 0;
                if (!(nq == 3 && j == 1)) {
                    float b0 = __ldg(bias + col), b1 = __ldg(bias + col + 1);
                    h0 = pk2(gelu_t(c[s][j][0] + b0), gelu_t(c[s][j][1] + b1));
                    h1 = pk2(gelu_t(c[s][j][2] + b0), gelu_t(c[s][j][3] + b1));
                }
                *(uint32_t*)(sm + dO + ((uint32_t)(r0 * LDA + col)) * 2)       = h0;
                *(uint32_t*)(sm + dO + ((uint32_t)((r0 + 8) * LDA + col)) * 2) = h1;
            }
        }
    }
}

template <bool ADDB>
__device__ __forceinline__ void row_cvt_ln(float* __restrict__ xs, const float* __restrict__ g,
                                           const float* __restrict__ b, const float* __restrict__ b2,
                                           char* sm, int tid) {
    int r = tid >> 2, part = tid & 3;
    float* xr = xs + r * LDF + part * 14;
    float v[14];
    #pragma unroll
    for (int j = 0; j < 7; j++) *(float2*)(v + 2 * j) = *(const float2*)(xr + 2 * j);
    float s = 0.f, ss = 0.f;
    #pragma unroll
    for (int j = 0; j < 14; j++) { s += v[j]; ss += v[j] * v[j]; }
    s  += __shfl_xor_sync(0xffffffffu, s, 1);
    ss += __shfl_xor_sync(0xffffffffu, ss, 1);
    s  += __shfl_xor_sync(0xffffffffu, s, 2);
    ss += __shfl_xor_sync(0xffffffffu, ss, 2);
    if (ADDB) {
        #pragma unroll
        for (int j = 0; j < 14; j++) xr[j] = v[j] + __ldg(b2 + part * 14 + j);
    }
    float m = s * (1.f / 56.f), rs = rsqrtf(ss * (1.f / 56.f) - m * m + 1e-5f);
    uint32_t* ah = (uint32_t*)(sm + AH_O + ((uint32_t)(r * LDA + part * 14)) * 2);
    #pragma unroll
    for (int t = 0; t < 7; t++) {
        int cl = part * 14 + 2 * t;
        float v0 = (v[2 * t]     - m) * rs * __ldg(g + cl)     + __ldg(b + cl);
        float v1 = (v[2 * t + 1] - m) * rs * __ldg(g + cl + 1) + __ldg(b + cl + 1);
        ah[t] = pk2(v0, v1);
    }
}

__global__ void __launch_bounds__(256, 2)
nbody_tc(const float* __restrict__ nodes, const float* __restrict__ edges,
         const float* __restrict__ mask,
         const float* __restrict__ W_in, const float* __restrict__ b_in,
         const float* __restrict__ W_gp, const float* __restrict__ b_gp,
         const float* __restrict__ ln1g, const float* __restrict__ ln1b,
         const float* __restrict__ ln2g, const float* __restrict__ ln2b,
         const float* __restrict__ b1, const float* __restrict__ b2,
         float* __restrict__ out, int Btot) {
    extern __shared__ char sm[];
    const int tid = threadIdx.x, bx = blockIdx.x;
    const uint32_t smb = (uint32_t)__cvta_generic_to_shared(sm);
    float* xs = (float*)(sm + XS_O);
    BR br;
    ldb(br, 0, tid);                        // Wq(l=0)

    #pragma unroll 1
    for (int i = tid; i < 64 * LDF / 4; i += 256) ((float4*)xs)[i] = make_float4(0.f, 0.f, 0.f, 0.f);
    if (tid < 64)                           // zero A-hi K-pad cols 56..63
        *(uint4*)(sm + AH_O + ((uint32_t)(tid * LDA + 56)) * 2) = make_uint4(0u, 0u, 0u, 0u);

    if (tid < 50) {
        int g = tid / 25, s = tid % 25;
        long Bi = (long)bx * 2 + g;
        if (Bi < Btot) {
            const float* sp = (s < 5) ? nodes + (Bi * 5 + s) * 24 : edges + (Bi * 20 + (s - 5)) * 24;
            float xin[24];
            #pragma unroll
            for (int i = 0; i < 24; i++) xin[i] = __ldg(sp + i);
            const int GR[8] = {0, 1, 1, 1, 2, 2, 2, 3};
            const int POS[8] = {0, 1, 2, 4, 3, 5, 6, 7};
            float* xrow = xs + (g * 32 + s) * LDF;
            #pragma unroll 1
            for (int n = 0; n < 7; n++) {
                float acc[8];
                #pragma unroll
                for (int i = 0; i < 8; i++) acc[i] = (i == 0) ? __ldg(b_gp + n) : 0.f;
                #pragma unroll 1
                for (int m = 0; m < 7; m++) {
                    float mv[8];
                    #pragma unroll
                    for (int i = 0; i < 8; i++) {
                        int gr = GR[i];
                        mv[i] = xin[i] * __ldg(W_in + m * 12 + gr) + xin[8 + i] * __ldg(W_in + m * 12 + 4 + gr)
                              + xin[16 + i] * __ldg(W_in + m * 12 + 8 + gr);
                    }
                    mv[0] += __ldg(b_in + m);
                    float gp[8];
                    #pragma unroll
                    for (int j = 0; j < 8; j++) gp[j] = 0.f;
                    #pragma unroll
                    for (int a = 0; a < 8; a++)
                        #pragma unroll
                        for (int bb = 0; bb < 8; bb++) {
                            int sc = 0;
                            #pragma unroll
                            for (int t = a >> 1; t; t >>= 1) sc += __popc(t & bb);
                            gp[POS[a ^ bb]] += ((sc & 1) ? -1.f : 1.f) * mv[POS[a]] * mv[POS[bb]];
                        }
                    #pragma unroll
                    for (int i = 0; i < 8; i++) {
                        int gr = GR[i];
                        acc[i] += mv[i] * __ldg(W_gp + n * 56 + m * 4 + gr)
                                + gp[i] * __ldg(W_gp + n * 56 + (m + 7) * 4 + gr);
                    }
                }
                #pragma unroll
                for (int i = 0; i < 8; i++) xrow[n * 8 + i] = acc[i];
            }
        }
    }
    __syncthreads();
    stb(sm, br, tid, B0H_O);   // B0 <- Wq(l=0)
    ldb(br, 1, tid);           // br <- Wk(l=0)
    __syncthreads();

    #pragma unroll 1
    for (int l = 0; l < 4; l++) {
        const int sbase = l * 12;
        const int nl = (l < 3) ? (sbase + 12) : 0;
        row_cvt_ln<false>(xs, ln1g + l * 56, ln1b + l * 56, nullptr, sm, tid);
        __syncthreads();

        // Q on B0 | stage B1<-Wk, fetch Wv
        stb(sm, br, tid, B1H_O); ldb(br, sbase + 2, tid);
        gemm_m<0>(sm, smb, AH_O, B0H_O, nullptr, QS_O, nullptr, tid);
        __syncthreads();
        // K on B1 | stage B0<-Wv, fetch Wo
        stb(sm, br, tid, B0H_O); ldb(br, sbase + 3, tid);
        gemm_m<0>(sm, smb, AH_O, B1H_O, nullptr, KS_O, nullptr, tid);
        __syncthreads();
        // V on B0 | stage B1<-Wo, fetch W1_0
        stb(sm, br, tid, B1H_O); ldb(br, sbase + 4, tid);
        gemm_m<0>(sm, smb, AH_O, B0H_O, nullptr, VS_O, nullptr, tid);
        __syncthreads();

        // broadcast attention on bf16 q/k/v: warp = (g, head), lane = query s
        {
            int lane = tid & 31, w = tid >> 5;
            #pragma unroll
            for (int rep = 0; rep < 2; rep++) {
                int pair = w + rep * 8;
                int g = pair >> 3, hh = pair & 7;
                long Bi = (long)bx * 2 + g;
                long Bic = (Bi < Btot) ? Bi : (long)(Btot - 1);
                int s = (lane < 25) ? lane : 24;
                uint32_t rqb = ((uint32_t)((g * 32 + s) * LDA + hh * 8)) * 2;
                uint4 qp = *(const uint4*)(sm + QS_O + rqb);
                float q0 = bf_lo(qp.x), q1 = bf_hi(qp.x), q2 = bf_lo(qp.y), q3 = bf_hi(qp.y);
                float q4 = bf_lo(qp.z), q5 = bf_hi(qp.z), q6 = bf_lo(qp.w), q7 = bf_hi(qp.w);
                const float* mrow = mask + (Bic * 25 + s) * 25;
                float sc[25]; float mx = -1e30f;
                #pragma unroll
                for (int ki = 0; ki < 25; ki++) {
                    uint4 kp = *(const uint4*)(sm + KS_O + ((uint32_t)((g * 32 + ki) * LDA + hh * 8)) * 2);
                    float dot = q0 * bf_lo(kp.x) + q1 * bf_hi(kp.x) + q2 * bf_lo(kp.y) + q3 * bf_hi(kp.y)
                              + q4 * bf_lo(kp.z) + q5 * bf_hi(kp.z) + q6 * bf_lo(kp.w) + q7 * bf_hi(kp.w);
                    sc[ki] = dot * 0.3779644730092272f + __ldg(mrow + ki);
                    mx = fmaxf(mx, sc[ki]);
                }
                float sum = 0.f;
                #pragma unroll
                for (int ki = 0; ki < 25; ki++) { float e = __expf(sc[ki] - mx); sc[ki] = e; sum += e; }
                float inv = 1.f / sum;
                float o0 = 0.f, o1 = 0.f, o2 = 0.f, o3 = 0.f, o4 = 0.f, o5 = 0.f, o6 = 0.f, o7 = 0.f;
                #pragma unroll
                for (int ki = 0; ki < 25; ki++) {
                    uint4 vp = *(const uint4*)(sm + VS_O + ((uint32_t)((g * 32 + ki) * LDA + hh * 8)) * 2);
                    float p = sc[ki];
                    o0 += p * bf_lo(vp.x); o1 += p * bf_hi(vp.x);
                    o2 += p * bf_lo(vp.y); o3 += p * bf_hi(vp.y);
                    o4 += p * bf_lo(vp.z); o5 += p * bf_hi(vp.z);
                    o6 += p * bf_lo(vp.w); o7 += p * bf_hi(vp.w);
                }
                if (lane < 25) {
                    uint32_t ob = ((uint32_t)((g * 32 + lane) * LDA + hh * 8)) * 2;
                    uint4 H;
                    H.x = pk2(o0 * inv, o1 * inv);
                    H.y = pk2(o2 * inv, o3 * inv);
                    H.z = pk2(o4 * inv, o5 * inv);
                    H.w = pk2(o6 * inv, o7 * inv);
                    *(uint4*)(sm + AH_O + ob) = H;
                }
            }
        }
        __syncthreads();

        // x += o @ Wo on B1 | stage B0<-W1_0, fetch W2_0
        stb(sm, br, tid, B0H_O); ldb(br, sbase + 8, tid);
        gemm_m<1>(sm, smb, AH_O, B1H_O, xs, 0u, nullptr, tid);
        __syncthreads();

        row_cvt_ln<true>(xs, ln2g + l * 56, ln2b + l * 56, b2 + l * 56, sm, tid);
        __syncthreads();

        #pragma unroll 1
        for (int c = 0; c < 4; c++) {
            // W1_c on B0 | stage B1<-W2_c, fetch W1_{c+1} (or next-layer Wq)
            stb(sm, br, tid, B1H_O);
            ldb(br, (c < 3) ? (sbase + 5 + c) : nl, tid);
            gemm_m<2>(sm, smb, AH_O, B0H_O, nullptr, A2H_O, b1 + l * 224 + c * 56, tid);
            __syncthreads();
            // W2_c on B1 | stage B0<-W1_{c+1}/Wq_next, fetch W2_{c+1} (or next-layer Wk)
            stb(sm, br, tid, B0H_O);
            ldb(br, (c < 3) ? (sbase + 9 + c) : (nl + 1), tid);
            gemm_m<1>(sm, smb, A2H_O, B1H_O, xs, 0u, nullptr, tid);
            __syncthreads();
        }
    }

    if (tid < 80) {
        int g = tid / 40, r = tid % 40, s = r / 8, i = r % 8;
        long Bi = (long)bx * 2 + g;
        if (Bi < Btot) out[(Bi * 5 + s) * 8 + i] = xs[(g * 32 + s) * LDF + 8 + i];
    }
}

extern "C" void kernel_launch(void* const* d_in, const int* in_sizes, int n_in,
                              void* d_out, int out_size) {
    int o = (n_in >= 20) ? 4 : 3;
    const float* nodes = (const float*)d_in[0];
    const float* edges = (const float*)d_in[1];
    const float* mask  = (const float*)d_in[2];
    const float* W_in  = (const float*)d_in[o + 0];
    const float* b_in  = (const float*)d_in[o + 1];
    const float* W_gp  = (const float*)d_in[o + 2];
    const float* b_gp  = (const float*)d_in[o + 3];
    const float* Wq    = (const float*)d_in[o + 4];
    const float* Wk    = (const float*)d_in[o + 5];
    const float* Wv    = (const float*)d_in[o + 6];
    const float* Wo    = (const float*)d_in[o + 7];
    const float* ln1g  = (const float*)d_in[o + 8];
    const float* ln1b  = (const float*)d_in[o + 9];
    const float* ln2g  = (const float*)d_in[o + 10];
    const float* ln2b  = (const float*)d_in[o + 11];
    const float* W1    = (const float*)d_in[o + 12];
    const float* b1    = (const float*)d_in[o + 13];
    const float* W2    = (const float*)d_in[o + 14];
    const float* b2    = (const float*)d_in[o + 15];

    int B = in_sizes[0] / 120;
    prep_weights<<<48, 256>>>(Wq, Wk, Wv, Wo, W1, W2);
    cudaFuncSetAttribute(nbody_tc, cudaFuncAttributeMaxDynamicSharedMemorySize, SMEMB);
    nbody_tc<<<(B + 1) / 2, 256, SMEMB>>>(nodes, edges, mask, W_in, b_in, W_gp, b_gp,
                                          ln1g, ln1b, ln2g, ln2b, b1, b2, (float*)d_out, B);
}